// round 13
// baseline (speedup 1.0000x reference)
#include <cuda_runtime.h>
#include <cuda_bf16.h>
#include <cstdint>

#define EPSm   1e-5f
#define NROWSm 131072
#define NTILESm 1024
#define NPART  1024

// ---------------- device scratch ----------------
__device__ float g_x[NROWSm * 128];
__device__ float g_part[NPART * 128 * 128];   // 64 MB gram partials (stage 0)
__device__ float g_part2[8 * 128 * 128];      // 512 KB (stage 1)
__device__ float g_QK[128 * 128];
__device__ float g_T1[128 * 128];
__device__ unsigned g_bar1;                   // device barrier (148 arrivals/step)
__device__ unsigned g_bar2;                   // worker barrier (32 arrivals/step)
__device__ __nv_bfloat16 g_Mt_hi[128 * 128],  g_Mt_lo[128 * 128];
__device__ __nv_bfloat16 g_w1t_hi[512 * 128], g_w1t_lo[512 * 128];   // [512 n][128 k]
__device__ __nv_bfloat16 g_w2t_hi[128 * 512], g_w2t_lo[128 * 512];   // [128 n][512 k]
__device__ __nv_bfloat16 g_owt_hi[128 * 128], g_owt_lo[128 * 128];

// ---------------- helpers ----------------
__device__ __forceinline__ uint32_t smem_u32(const void* p) {
    uint32_t a;
    asm("{ .reg .u64 t; cvta.to.shared.u64 t, %1; cvt.u32.u64 %0, t; }" : "=r"(a) : "l"(p));
    return a;
}
// XOR-swizzled tile, 256B rows (128 bf16 cols)
__device__ __forceinline__ uint32_t sw16(int r, int c8) {
    return (uint32_t)(r * 256 + ((c8 ^ (r & 7)) << 4));
}
__device__ __forceinline__ uint32_t sw4(int r, int col) {
    return (uint32_t)(r * 256 + ((((col >> 3) ^ (r & 7)) << 4)) + (col & 7) * 2);
}
// XOR-swizzled tile, 128B rows (64 bf16 cols)
__device__ __forceinline__ uint32_t sw16_64(int r, int c8) {
    return (uint32_t)(r * 128 + ((((c8 ^ (r & 7)) & 7) << 4)));
}
__device__ __forceinline__ uint32_t sw4_64(int r, int col) {
    return (uint32_t)(r * 128 + ((((col >> 3) ^ (r & 7)) & 7) << 4) + (col & 7) * 2);
}
__device__ __forceinline__ void split2(float f0, float f1, uint32_t& hi, uint32_t& lo) {
    __nv_bfloat162 H = __floats2bfloat162_rn(f0, f1);
    float r0 = f0 - __bfloat162float(H.x);
    float r1 = f1 - __bfloat162float(H.y);
    __nv_bfloat162 L = __floats2bfloat162_rn(r0, r1);
    hi = *reinterpret_cast<uint32_t*>(&H);
    lo = *reinterpret_cast<uint32_t*>(&L);
}
__device__ __forceinline__ void sp1(float v, __nv_bfloat16* h, __nv_bfloat16* l) {
    __nv_bfloat16 hh = __float2bfloat16(v);
    *h = hh;
    *l = __float2bfloat16(v - __bfloat162float(hh));
}
__device__ __forceinline__ void ldsm4(uint32_t* r, uint32_t a) {
    asm volatile("ldmatrix.sync.aligned.m8n8.x4.shared.b16 {%0,%1,%2,%3}, [%4];"
                 : "=r"(r[0]), "=r"(r[1]), "=r"(r[2]), "=r"(r[3]) : "r"(a));
}
__device__ __forceinline__ void ldsm2(uint32_t* r, uint32_t a) {
    asm volatile("ldmatrix.sync.aligned.m8n8.x2.shared.b16 {%0,%1}, [%2];"
                 : "=r"(r[0]), "=r"(r[1]) : "r"(a));
}
__device__ __forceinline__ void ldsm4t(uint32_t* r, uint32_t a) {
    asm volatile("ldmatrix.sync.aligned.m8n8.x4.trans.shared.b16 {%0,%1,%2,%3}, [%4];"
                 : "=r"(r[0]), "=r"(r[1]), "=r"(r[2]), "=r"(r[3]) : "r"(a));
}
__device__ __forceinline__ void ldsm2t(uint32_t* r, uint32_t a) {
    asm volatile("ldmatrix.sync.aligned.m8n8.x2.trans.shared.b16 {%0,%1}, [%2];"
                 : "=r"(r[0]), "=r"(r[1]) : "r"(a));
}
__device__ __forceinline__ void mma_bf16(float* c, const uint32_t* a, const uint32_t* b) {
    asm volatile(
        "mma.sync.aligned.m16n8k16.row.col.f32.bf16.bf16.f32 "
        "{%0,%1,%2,%3}, {%4,%5,%6,%7}, {%8,%9}, {%0,%1,%2,%3};"
        : "+f"(c[0]), "+f"(c[1]), "+f"(c[2]), "+f"(c[3])
        : "r"(a[0]), "r"(a[1]), "r"(a[2]), "r"(a[3]), "r"(b[0]), "r"(b[1]));
}
// ---- cp.async ----
__device__ __forceinline__ void cpa16(uint32_t dst, const void* src) {
    asm volatile("cp.async.cg.shared.global [%0], [%1], 16;" :: "r"(dst), "l"(src));
}
__device__ __forceinline__ void cpa_commit() { asm volatile("cp.async.commit_group;"); }
template<int N> __device__ __forceinline__ void cpa_wait() {
    asm volatile("cp.async.wait_group %0;" :: "n"(N));
}
// nrows x 256B swizzled tile via cp.async (256 threads)
__device__ __forceinline__ void cp_tile256(uint32_t dst, const uint4* __restrict__ src,
                                           int nrows, int rs_u4, int tid) {
    int n = nrows * 16;
    for (int idx = tid; idx < n; idx += 256) {
        int r = idx >> 4, c8 = idx & 15;
        cpa16(dst + sw16(r, c8), src + r * rs_u4 + c8);
    }
}
// 128 rows x 128B swizzled tile via cp.async
__device__ __forceinline__ void cp_tile128(uint32_t dst, const uint4* __restrict__ src,
                                           int rs_u4, int tid) {
#pragma unroll
    for (int i = 0; i < 4; ++i) {
        int idx = tid + i * 256;
        int r = idx >> 3, c8 = idx & 7;
        cpa16(dst + sw16_64(r, c8), src + r * rs_u4 + c8);
    }
}

// C[128][128] += A(128x128k) @ Bt(128n x 128k)^T, bf16 3-split (256B-row tiles)
__device__ __forceinline__ void mma_nt(float (&acc)[4][4][4],
                                       uint32_t aHi, uint32_t aLo,
                                       uint32_t bHi, uint32_t bLo,
                                       int warp_m, int warp_n, int lane) {
#pragma unroll
    for (int k8 = 0; k8 < 8; ++k8) {
        uint32_t aH[4][4], aL[4][4], bH[4][2], bL[4][2];
        int ar = warp_m * 64 + (lane & 15);
        int ac8 = k8 * 2 + (lane >> 4);
#pragma unroll
        for (int mi = 0; mi < 4; ++mi) {
            uint32_t off = sw16(ar + mi * 16, ac8);
            ldsm4(aH[mi], aHi + off);
            ldsm4(aL[mi], aLo + off);
        }
        int l15 = lane & 15;
        int br = warp_n * 32 + (l15 & 7);
        int bc8 = k8 * 2 + (l15 >> 3);
#pragma unroll
        for (int ni = 0; ni < 4; ++ni) {
            uint32_t off = sw16(br + ni * 8, bc8);
            ldsm2(bH[ni], bHi + off);
            ldsm2(bL[ni], bLo + off);
        }
#pragma unroll
        for (int mi = 0; mi < 4; ++mi)
#pragma unroll
            for (int ni = 0; ni < 4; ++ni) {
                mma_bf16(acc[mi][ni], aH[mi], bH[ni]);
                mma_bf16(acc[mi][ni], aH[mi], bL[ni]);
                mma_bf16(acc[mi][ni], aL[mi], bH[ni]);
            }
    }
}

// u[128][64] = A(128x128k) @ Bt(64n x 128k)^T  (B tile 64 rows, 256B rows)
__device__ __forceinline__ void mma_n64(float (&u)[4][2][4],
                                        uint32_t aHi, uint32_t aLo,
                                        uint32_t bHi, uint32_t bLo,
                                        int warp_m, int warp_n, int lane) {
#pragma unroll
    for (int k8 = 0; k8 < 8; ++k8) {
        uint32_t aH[4][4], aL[4][4], bH[2][2], bL[2][2];
        int ar = warp_m * 64 + (lane & 15);
        int ac8 = k8 * 2 + (lane >> 4);
#pragma unroll
        for (int mi = 0; mi < 4; ++mi) {
            uint32_t off = sw16(ar + mi * 16, ac8);
            ldsm4(aH[mi], aHi + off);
            ldsm4(aL[mi], aLo + off);
        }
        int l15 = lane & 15;
        int br = warp_n * 16 + (l15 & 7);
        int bc8 = k8 * 2 + (l15 >> 3);
#pragma unroll
        for (int ni = 0; ni < 2; ++ni) {
            uint32_t off = sw16(br + ni * 8, bc8);
            ldsm2(bH[ni], bHi + off);
            ldsm2(bL[ni], bLo + off);
        }
#pragma unroll
        for (int mi = 0; mi < 4; ++mi)
#pragma unroll
            for (int ni = 0; ni < 2; ++ni) {
                mma_bf16(u[mi][ni], aH[mi], bH[ni]);
                mma_bf16(u[mi][ni], aH[mi], bL[ni]);
                mma_bf16(u[mi][ni], aL[mi], bH[ni]);
            }
    }
}

// C[128][128] += F(128m x 64k) @ Bt(128n x 64k)^T  (128B-row tiles)
__device__ __forceinline__ void mma_k64(float (&acc)[4][4][4],
                                        uint32_t fHi, uint32_t fLo,
                                        uint32_t bHi, uint32_t bLo,
                                        int warp_m, int warp_n, int lane) {
#pragma unroll
    for (int k8 = 0; k8 < 4; ++k8) {
        uint32_t aH[4][4], aL[4][4], bH[4][2], bL[4][2];
        int ar = warp_m * 64 + (lane & 15);
        int ac8 = k8 * 2 + (lane >> 4);
#pragma unroll
        for (int mi = 0; mi < 4; ++mi) {
            uint32_t off = sw16_64(ar + mi * 16, ac8);
            ldsm4(aH[mi], fHi + off);
            ldsm4(aL[mi], fLo + off);
        }
        int l15 = lane & 15;
        int br = warp_n * 32 + (l15 & 7);
        int bc8 = k8 * 2 + (l15 >> 3);
#pragma unroll
        for (int ni = 0; ni < 4; ++ni) {
            uint32_t off = sw16_64(br + ni * 8, bc8);
            ldsm2(bH[ni], bHi + off);
            ldsm2(bL[ni], bLo + off);
        }
#pragma unroll
        for (int mi = 0; mi < 4; ++mi)
#pragma unroll
            for (int ni = 0; ni < 4; ++ni) {
                mma_bf16(acc[mi][ni], aH[mi], bH[ni]);
                mma_bf16(acc[mi][ni], aH[mi], bL[ni]);
                mma_bf16(acc[mi][ni], aL[mi], bH[ni]);
            }
    }
}

// Gram: C += H^T @ H, bf16 3-split; trans loads of row-major H tile.
__device__ __forceinline__ void mma_tt(float (&acc)[4][4][4],
                                       uint32_t hHi, uint32_t hLo,
                                       int warp_m, int warp_n, int lane) {
#pragma unroll
    for (int k8 = 0; k8 < 8; ++k8) {
        int k0 = k8 * 16;
        uint32_t aH[4][4], aL[4][4], bH[4][2], bL[4][2];
        int ar = k0 + (lane & 7) + ((lane >> 4) << 3);
        int asel = (lane >> 3) & 1;
#pragma unroll
        for (int mi = 0; mi < 4; ++mi) {
            int c8 = ((warp_m * 64 + mi * 16) >> 3) + asel;
            uint32_t off = sw16(ar, c8);
            ldsm4t(aH[mi], hHi + off);
            ldsm4t(aL[mi], hLo + off);
        }
        int l15 = lane & 15;
        int br = k0 + (l15 & 7) + ((l15 >> 3) << 3);
#pragma unroll
        for (int ni = 0; ni < 4; ++ni) {
            int c8 = (warp_n * 32 + ni * 8) >> 3;
            uint32_t off = sw16(br, c8);
            ldsm2t(bH[ni], hHi + off);
            ldsm2t(bL[ni], hLo + off);
        }
#pragma unroll
        for (int mi = 0; mi < 4; ++mi)
#pragma unroll
            for (int ni = 0; ni < 4; ++ni) {
                mma_bf16(acc[mi][ni], aH[mi], bH[ni]);
                mma_bf16(acc[mi][ni], aH[mi], bL[ni]);
                mma_bf16(acc[mi][ni], aL[mi], bH[ni]);
            }
    }
}

// LayerNorm of fragment-layout values -> split hi/lo into swizzled 256B-row tile.
template<bool ENDSYNC>
__device__ __forceinline__ void ln_acc(const float (&v)[4][4][4],
                                       const float* gs, const float* bs,
                                       char* Ahi, char* Alo,
                                       float2* red,
                                       int warp_m, int warp_n, int lane, int tid) {
    int row0 = warp_m * 64 + (lane >> 2);
    int col0 = warp_n * 32 + (lane & 3) * 2;
#pragma unroll
    for (int mi = 0; mi < 4; ++mi) {
        float s1 = 0, q1 = 0, s2 = 0, q2 = 0;
#pragma unroll
        for (int ni = 0; ni < 4; ++ni) {
            s1 += v[mi][ni][0] + v[mi][ni][1];
            q1 += v[mi][ni][0] * v[mi][ni][0] + v[mi][ni][1] * v[mi][ni][1];
            s2 += v[mi][ni][2] + v[mi][ni][3];
            q2 += v[mi][ni][2] * v[mi][ni][2] + v[mi][ni][3] * v[mi][ni][3];
        }
        s1 += __shfl_xor_sync(~0u, s1, 1); s1 += __shfl_xor_sync(~0u, s1, 2);
        q1 += __shfl_xor_sync(~0u, q1, 1); q1 += __shfl_xor_sync(~0u, q1, 2);
        s2 += __shfl_xor_sync(~0u, s2, 1); s2 += __shfl_xor_sync(~0u, s2, 2);
        q2 += __shfl_xor_sync(~0u, q2, 1); q2 += __shfl_xor_sync(~0u, q2, 2);
        if ((lane & 3) == 0) {
            int r1 = row0 + mi * 16;
            red[r1 * 4 + warp_n] = make_float2(s1, q1);
            red[(r1 + 8) * 4 + warp_n] = make_float2(s2, q2);
        }
    }
    __syncthreads();
#pragma unroll
    for (int mi = 0; mi < 4; ++mi) {
        int r1 = row0 + mi * 16;
        float s1 = 0, q1 = 0, s2 = 0, q2 = 0;
#pragma unroll
        for (int w = 0; w < 4; ++w) {
            float2 p1 = red[r1 * 4 + w];
            float2 p2 = red[(r1 + 8) * 4 + w];
            s1 += p1.x; q1 += p1.y;
            s2 += p2.x; q2 += p2.y;
        }
        float m1 = s1 * (1.0f / 128.0f);
        float rs1 = rsqrtf(q1 * (1.0f / 128.0f) - m1 * m1 + EPSm);
        float m2 = s2 * (1.0f / 128.0f);
        float rs2 = rsqrtf(q2 * (1.0f / 128.0f) - m2 * m2 + EPSm);
#pragma unroll
        for (int ni = 0; ni < 4; ++ni) {
            int col = col0 + ni * 8;
            float g0 = gs[col], g1 = gs[col + 1], bb0 = bs[col], bb1 = bs[col + 1];
            int r2 = r1 + 8;
            float f0 = (v[mi][ni][0] - m1) * rs1 * g0 + bb0;
            float f1 = (v[mi][ni][1] - m1) * rs1 * g1 + bb1;
            float f2 = (v[mi][ni][2] - m2) * rs2 * g0 + bb0;
            float f3 = (v[mi][ni][3] - m2) * rs2 * g1 + bb1;
            uint32_t h, l;
            uint32_t o1 = sw4(r1, col), o2 = sw4(r2, col);
            split2(f0, f1, h, l);
            *reinterpret_cast<uint32_t*>(Ahi + o1) = h;
            *reinterpret_cast<uint32_t*>(Alo + o1) = l;
            split2(f2, f3, h, l);
            *reinterpret_cast<uint32_t*>(Ahi + o2) = h;
            *reinterpret_cast<uint32_t*>(Alo + o2) = l;
        }
    }
    if (ENDSYNC) __syncthreads();
}

// ============================ kernels ============================

__global__ void kprep_kernel(const float* __restrict__ w1, const float* __restrict__ w2,
                             const float* __restrict__ outw) {
    int idx = blockIdx.x * 256 + threadIdx.x;
    if (idx < 65536) {                 // w1t [512 n][128 k]
        int n = idx >> 7, k = idx & 127;
        sp1(w1[k * 512 + n], &g_w1t_hi[idx], &g_w1t_lo[idx]);
    } else if (idx < 131072) {         // w2t [128 n][512 k]
        int j = idx - 65536;
        int n = j >> 9, k = j & 511;
        sp1(w2[k * 128 + n], &g_w2t_hi[j], &g_w2t_lo[j]);
    } else if (idx < 147456) {         // owt [128 n][128 k]
        int j = idx - 131072;
        int n = j >> 7, k = j & 127;
        sp1(outw[k * 128 + n], &g_owt_hi[j], &g_owt_lo[j]);
    }
}

// t=0 Gram partials: one 128-row tile per CTA; h = LN1(x); part = h^T h.
#define KG_SMEM (6144 + 65536)
__global__ void __launch_bounds__(256, 1)
kgram0(const float* __restrict__ xin,
       const float* __restrict__ lng, const float* __restrict__ lnb) {
    extern __shared__ char sm[];
    float* gs = reinterpret_cast<float*>(sm);
    float* bs = gs + 128;
    float2* red = reinterpret_cast<float2*>(sm + 1024);
    char* Hhi = sm + 6144;
    char* Hlo = sm + 6144 + 32768;
    uint32_t smb = smem_u32(sm);
    int tid = threadIdx.x, lane = tid & 31, wid = tid >> 5;
    int warp_m = wid & 1, warp_n = wid >> 1;
    int row0 = warp_m * 64 + (lane >> 2);
    int col0 = warp_n * 32 + (lane & 3) * 2;
    if (tid < 128) { gs[tid] = lng[tid]; bs[tid] = lnb[tid]; }
    __syncthreads();

    const float* xt = xin + (size_t)blockIdx.x * 16384;
    float v[4][4][4];
#pragma unroll
    for (int mi = 0; mi < 4; ++mi)
#pragma unroll
        for (int ni = 0; ni < 4; ++ni) {
            const float* p = xt + (row0 + mi * 16) * 128 + col0 + ni * 8;
            float2 a = *reinterpret_cast<const float2*>(p);
            float2 b = *reinterpret_cast<const float2*>(p + 8 * 128);
            v[mi][ni][0] = a.x; v[mi][ni][1] = a.y;
            v[mi][ni][2] = b.x; v[mi][ni][3] = b.y;
        }
    ln_acc<true>(v, gs, bs, Hhi, Hlo, red, warp_m, warp_n, lane, tid);

    float acc[4][4][4];
#pragma unroll
    for (int mi = 0; mi < 4; ++mi)
#pragma unroll
        for (int ni = 0; ni < 4; ++ni)
#pragma unroll
            for (int e = 0; e < 4; ++e) acc[mi][ni][e] = 0.f;
    mma_tt(acc, smb + 6144, smb + 6144 + 32768, warp_m, warp_n, lane);

    float* dst = g_part + (size_t)blockIdx.x * 16384;
#pragma unroll
    for (int mi = 0; mi < 4; ++mi)
#pragma unroll
        for (int ni = 0; ni < 4; ++ni) {
            int r1 = row0 + mi * 16, col = col0 + ni * 8;
            __stcs(reinterpret_cast<float2*>(dst + r1 * 128 + col),
                   make_float2(acc[mi][ni][0], acc[mi][ni][1]));
            __stcs(reinterpret_cast<float2*>(dst + (r1 + 8) * 128 + col),
                   make_float2(acc[mi][ni][2], acc[mi][ni][3]));
        }
}

// one-shot QK = Qw @ Kw^T (launch-time prep)
#define TS_SMEM (128 * 129 * 4 + 512 * 4)
__global__ void __launch_bounds__(256, 1)
kqk_kernel(const float* __restrict__ A, const float* __restrict__ B) {
    extern __shared__ float ts[];
    float* Bs = ts;
    float* As = ts + 128 * 129;
    int tid = threadIdx.x;
    for (int idx = tid; idx < 16384; idx += 256)
        Bs[(idx >> 7) * 129 + (idx & 127)] = B[idx];
    int r0 = blockIdx.x * 4;
    for (int idx = tid; idx < 512; idx += 256)
        As[idx] = A[(r0 + (idx >> 7)) * 128 + (idx & 127)];
    __syncthreads();
    int j = tid & 127, i0 = (tid >> 7) * 2;
    float c0 = 0.f, c1 = 0.f;
#pragma unroll 8
    for (int k = 0; k < 128; ++k) {
        float b = Bs[j * 129 + k];
        c0 = fmaf(As[i0 * 128 + k], b, c0);
        c1 = fmaf(As[i0 * 128 + 128 + k], b, c1);
    }
    g_QK[(r0 + i0) * 128 + j] = c0;
    g_QK[(r0 + i0 + 1) * 128 + j] = c1;
}

// ===== fused per-step reduce + mid kernel (persistent, 148 CTAs) =====
// Phase A (all CTAs): reduce 1024 gram partials -> 8 slabs (g_part2).
// Device barrier #1. Phase B (CTAs 0..31): T1 = G @ Vw (8-slab sum fused).
// Worker barrier #2. Phase C: Mt = split(QK @ T1).
__global__ void __launch_bounds__(256, 1)
kgm_kernel(const float* __restrict__ Vw) {
    extern __shared__ float ts[];
    float* Bs = ts;                 // [128][129]
    float* As = ts + 128 * 129;     // [4][128]
    int tid = threadIdx.x;
    int cta = blockIdx.x;
    bool worker = (cta < 32);

    // ---- phase A: grid-stride over 131072 (e,g) jobs; each sums 128 partials
    for (int job = cta * 256 + tid; job < 131072; job += 148 * 256) {
        int e = job & 16383;
        int g = job >> 14;                          // 0..7
        const float* p = g_part + (size_t)g * 128 * 16384 + e;
        float s0 = 0.f, s1 = 0.f, s2 = 0.f, s3 = 0.f;
#pragma unroll 8
        for (int i = 0; i < 128; i += 4) {
            s0 += __ldcs(p + (size_t)(i + 0) * 16384);
            s1 += __ldcs(p + (size_t)(i + 1) * 16384);
            s2 += __ldcs(p + (size_t)(i + 2) * 16384);
            s3 += __ldcs(p + (size_t)(i + 3) * 16384);
        }
        g_part2[(size_t)g * 16384 + e] = (s0 + s1) + (s2 + s3);
    }
    // workers preload Vw into Bs (overlaps other CTAs' phase A)
    if (worker) {
        for (int idx = tid; idx < 16384; idx += 256)
            Bs[(idx >> 7) * 129 + (idx & 127)] = Vw[idx];
    }
    // ---- device barrier #1 (148 arrivals; non-workers arrive and exit)
    __threadfence();
    __syncthreads();
    if (!worker) {
        if (tid == 0) atomicAdd(&g_bar1, 1u);
        return;
    }
    if (tid == 0) {
        unsigned arrive = atomicAdd(&g_bar1, 1u);
        unsigned target = (arrive / 148u + 1u) * 148u;
        while (*reinterpret_cast<volatile unsigned*>(&g_bar1) < target)
            __nanosleep(64);
        __threadfence();
    }
    __syncthreads();

    // ---- phase B: T1 = G @ Vw  (G rows summed from 8 slabs)
    int r0 = cta * 4;
    int j = tid & 127, i0 = (tid >> 7) * 2;
    for (int idx = tid; idx < 512; idx += 256) {
        int off = (r0 + (idx >> 7)) * 128 + (idx & 127);
        const float* p = g_part2 + off;
        float s = 0.f;
#pragma unroll
        for (int g = 0; g < 8; ++g) s += p[(size_t)g * 16384];
        As[idx] = s;
    }
    __syncthreads();
    {
        float c0 = 0.f, c1 = 0.f;
#pragma unroll 8
        for (int k = 0; k < 128; ++k) {
            float b = Bs[k * 129 + j];
            c0 = fmaf(As[i0 * 128 + k], b, c0);
            c1 = fmaf(As[i0 * 128 + 128 + k], b, c1);
        }
        g_T1[(r0 + i0) * 128 + j] = c0;
        g_T1[(r0 + i0 + 1) * 128 + j] = c1;
    }
    // ---- worker barrier #2 (32 arrivals)
    __threadfence();
    __syncthreads();
    if (tid == 0) {
        unsigned arrive = atomicAdd(&g_bar2, 1u);
        unsigned target = (arrive / 32u + 1u) * 32u;
        while (*reinterpret_cast<volatile unsigned*>(&g_bar2) < target)
            __nanosleep(64);
        __threadfence();
    }
    __syncthreads();
    // ---- phase C: Mt = split(QK @ T1)
    for (int idx = tid; idx < 16384; idx += 256)
        Bs[(idx >> 7) * 129 + (idx & 127)] = __ldcg(g_T1 + idx);
    for (int idx = tid; idx < 512; idx += 256)
        As[idx] = g_QK[(r0 + (idx >> 7)) * 128 + (idx & 127)];
    __syncthreads();
    {
        float c0 = 0.f, c1 = 0.f;
#pragma unroll 8
        for (int k = 0; k < 128; ++k) {
            float b = Bs[k * 129 + j];
            c0 = fmaf(As[i0 * 128 + k], b, c0);
            c1 = fmaf(As[i0 * 128 + 128 + k], b, c1);
        }
        sp1(c0, &g_Mt_hi[j * 128 + r0 + i0], &g_Mt_lo[j * 128 + r0 + i0]);
        sp1(c1, &g_Mt_hi[j * 128 + r0 + i0 + 1], &g_Mt_lo[j * 128 + r0 + i0 + 1]);
    }
}

// ================= big fused kernel (HMMA + cp.async, 2-sync FF pipeline) =================
#define KC_RED  5120
#define KC_A    10240                  // Ahi 32K | Alo 32K
#define KC_B0   (KC_A + 65536)         // 32K (hi at +0, lo at +16384 for FF tiles)
#define KC_B1   (KC_B0 + 32768)
#define KC_F    (KC_B1 + 32768)        // Fhi 16K | Flo 16K
#define KC_SMEM (KC_F + 32768)         // 174080

__global__ void __launch_bounds__(256, 1)
kc_mma(const float* __restrict__ xin, int srcIsG,
       const float* __restrict__ ln1g, const float* __restrict__ ln1b,
       const float* __restrict__ ln2g, const float* __restrict__ ln2b,
       const float* __restrict__ b1, const float* __restrict__ b2,
       const float* __restrict__ outb, float* __restrict__ outp, int last) {
    extern __shared__ char sm[];
    uint32_t smb = smem_u32(sm);
    int tid = threadIdx.x, lane = tid & 31, wid = tid >> 5;
    int warp_m = wid & 1, warp_n = wid >> 1;
    int row0 = warp_m * 64 + (lane >> 2);
    int col0 = warp_n * 32 + (lane & 3) * 2;

    float* ln1gs = reinterpret_cast<float*>(sm);
    float* ln1bs = ln1gs + 128;
    float* ln2gs = ln1gs + 256;
    float* ln2bs = ln1gs + 384;
    float* b2s   = ln1gs + 512;
    float* outbs = ln1gs + 640;
    float* b1s   = ln1gs + 768;     // 512 floats
    float2* red  = reinterpret_cast<float2*>(sm + KC_RED);
    if (tid < 128) {
        ln1gs[tid] = ln1g[tid]; ln1bs[tid] = ln1b[tid];
        ln2gs[tid] = ln2g[tid]; ln2bs[tid] = ln2b[tid];
        b2s[tid] = b2[tid]; outbs[tid] = outb[tid];
    }
    b1s[tid] = b1[tid]; b1s[tid + 256] = b1[tid + 256];

    // prefetch Mt (hi -> B0, lo -> B1), overlapped with x load + LN1
    cp_tile256(smb + KC_B0, reinterpret_cast<const uint4*>(g_Mt_hi), 128, 16, tid);
    cp_tile256(smb + KC_B1, reinterpret_cast<const uint4*>(g_Mt_lo), 128, 16, tid);
    cpa_commit();

    // x in fragment layout
    size_t base = (size_t)blockIdx.x * 16384;
    const float* xt = (srcIsG ? g_x : xin) + base;
    float xr[4][4][4];
#pragma unroll
    for (int mi = 0; mi < 4; ++mi)
#pragma unroll
        for (int ni = 0; ni < 4; ++ni) {
            const float* p = xt + (row0 + mi * 16) * 128 + col0 + ni * 8;
            float2 a = *reinterpret_cast<const float2*>(p);
            float2 b = *reinterpret_cast<const float2*>(p + 8 * 128);
            xr[mi][ni][0] = a.x; xr[mi][ni][1] = a.y;
            xr[mi][ni][2] = b.x; xr[mi][ni][3] = b.y;
        }

    // A <- LN1(x)  (end-sync folded into the cpa_wait sync below)
    ln_acc<false>(xr, ln1gs, ln1bs, sm + KC_A, sm + KC_A + 32768, red, warp_m, warp_n, lane, tid);
    cpa_wait<0>();
    __syncthreads();
    // x += h @ M
    mma_nt(xr, smb + KC_A, smb + KC_A + 32768, smb + KC_B0, smb + KC_B1, warp_m, warp_n, lane);
    __syncthreads();

    // prime FF pipeline: w1 sub-chunk 0 -> B0
    cp_tile256(smb + KC_B0,         reinterpret_cast<const uint4*>(g_w1t_hi), 64, 16, tid);
    cp_tile256(smb + KC_B0 + 16384, reinterpret_cast<const uint4*>(g_w1t_lo), 64, 16, tid);
    cpa_commit();

    // A <- LN2(x)  (end-sync folded into the cpa_wait sync below)
    ln_acc<false>(xr, ln2gs, ln2bs, sm + KC_A, sm + KC_A + 32768, red, warp_m, warp_n, lane, tid);
    cpa_wait<0>();       // w1_0 landed
    __syncthreads();     // w1_0 + A visible

    // FF: 8 sub-chunks of 64 hidden units, double-buffered weights, 2 syncs/iter
#pragma unroll 1
    for (int c = 0; c < 8; ++c) {
        // prefetch w2_c -> B1 (overlaps mma1 + relu)
        cp_tile128(smb + KC_B1,         reinterpret_cast<const uint4*>(g_w2t_hi) + c * 8, 64, tid);
        cp_tile128(smb + KC_B1 + 16384, reinterpret_cast<const uint4*>(g_w2t_lo) + c * 8, 64, tid);
        cpa_commit();
        float u[4][2][4];
#pragma unroll
        for (int mi = 0; mi < 4; ++mi)
#pragma unroll
            for (int ni = 0; ni < 2; ++ni)
#pragma unroll
                for (int e = 0; e < 4; ++e) u[mi][ni][e] = 0.f;
        mma_n64(u, smb + KC_A, smb + KC_A + 32768, smb + KC_B0, smb + KC_B0 + 16384,
                warp_m, warp_n, lane);
        // bias + relu + split -> F
#pragma unroll
        for (int mi = 0; mi < 4; ++mi)
#pragma unroll
            for (int ni = 0; ni < 2; ++ni) {
                int hcol = warp_n * 16 + (lane & 3) * 2 + ni * 8;      // 0..63
                float bb0 = b1s[c * 64 + hcol], bb1 = b1s[c * 64 + hcol + 1];
                int r1 = row0 + mi * 16, r2 = r1 + 8;
                float f0 = fmaxf(u[mi][ni][0] + bb0, 0.f);
                float f1 = fmaxf(u[mi][ni][1] + bb1, 0.f);
                float f2 = fmaxf(u[mi][ni][2] + bb0, 0.f);
                float f3 = fmaxf(u[mi][ni][3] + bb1, 0.f);
                uint32_t h, l;
                uint32_t o1 = sw4_64(r1, hcol), o2 = sw4_64(r2, hcol);
                split2(f0, f1, h, l);
                *reinterpret_cast<uint32_t*>(sm + KC_F + o1) = h;
                *reinterpret_cast<uint32_t*>(sm + KC_F + 16384 + o1) = l;
                split2(f2, f3, h, l);
                *reinterpret_cast<uint32_t*>(sm + KC_F + o2) = h;
                *reinterpret_cast<uint32_t*>(sm + KC_F + 16384 + o2) = l;
            }
        cpa_wait<0>();       // w2_c landed
        __syncthreads();     // F + w2_c visible; B0 (w1_c) free
        // prefetch w1_{c+1} -> B0 (overlaps mma2); last iter: owt_hi if needed
        if (c < 7) {
            cp_tile256(smb + KC_B0,         reinterpret_cast<const uint4*>(g_w1t_hi) + (c + 1) * 1024, 64, 16, tid);
            cp_tile256(smb + KC_B0 + 16384, reinterpret_cast<const uint4*>(g_w1t_lo) + (c + 1) * 1024, 64, 16, tid);
        } else if (last) {
            cp_tile256(smb + KC_B0, reinterpret_cast<const uint4*>(g_owt_hi), 128, 16, tid);
        }
        cpa_commit();
        mma_k64(xr, smb + KC_F, smb + KC_F + 16384, smb + KC_B1, smb + KC_B1 + 16384,
                warp_m, warp_n, lane);
        cpa_wait<0>();       // w1_{c+1} (or owt_hi) landed
        __syncthreads();     // B1/F free; next tile visible
    }

    // + b2
#pragma unroll
    for (int mi = 0; mi < 4; ++mi)
#pragma unroll
        for (int ni = 0; ni < 4; ++ni) {
            int col = col0 + ni * 8;
            xr[mi][ni][0] += b2s[col];     xr[mi][ni][1] += b2s[col + 1];
            xr[mi][ni][2] += b2s[col];     xr[mi][ni][3] += b2s[col + 1];
        }

    if (!last) {
        // store x_new
        float* dst = g_x + base;
#pragma unroll
        for (int mi = 0; mi < 4; ++mi)
#pragma unroll
            for (int ni = 0; ni < 4; ++ni) {
                int r1 = row0 + mi * 16, col = col0 + ni * 8;
                *reinterpret_cast<float2*>(dst + r1 * 128 + col) =
                    make_float2(xr[mi][ni][0], xr[mi][ni][1]);
                *reinterpret_cast<float2*>(dst + (r1 + 8) * 128 + col) =
                    make_float2(xr[mi][ni][2], xr[mi][ni][3]);
            }
        // fused Gram partial for the NEXT step: h = LN1(x_new); part = h^T h
        ln_acc<true>(xr, ln1gs, ln1bs, sm + KC_A, sm + KC_A + 32768, red, warp_m, warp_n, lane, tid);
        float ga[4][4][4];
#pragma unroll
        for (int mi = 0; mi < 4; ++mi)
#pragma unroll
            for (int ni = 0; ni < 4; ++ni)
#pragma unroll
                for (int e = 0; e < 4; ++e) ga[mi][ni][e] = 0.f;
        mma_tt(ga, smb + KC_A, smb + KC_A + 32768, warp_m, warp_n, lane);
        float* pdst = g_part + (size_t)blockIdx.x * 16384;
#pragma unroll
        for (int mi = 0; mi < 4; ++mi)
#pragma unroll
            for (int ni = 0; ni < 4; ++ni) {
                int r1 = row0 + mi * 16, col = col0 + ni * 8;
                __stcs(reinterpret_cast<float2*>(pdst + r1 * 128 + col),
                       make_float2(ga[mi][ni][0], ga[mi][ni][1]));
                __stcs(reinterpret_cast<float2*>(pdst + (r1 + 8) * 128 + col),
                       make_float2(ga[mi][ni][2], ga[mi][ni][3]));
            }
    } else {
        // out = x @ outw + outb  (owt_hi already landed in B0 at loop end)
        cp_tile256(smb + KC_B1, reinterpret_cast<const uint4*>(g_owt_lo), 128, 16, tid);
        cpa_commit();
        // split x -> A
#pragma unroll
        for (int mi = 0; mi < 4; ++mi)
#pragma unroll
            for (int ni = 0; ni < 4; ++ni) {
                int col = col0 + ni * 8;
                int r1 = row0 + mi * 16, r2 = r1 + 8;
                uint32_t h, l;
                uint32_t o1 = sw4(r1, col), o2 = sw4(r2, col);
                split2(xr[mi][ni][0], xr[mi][ni][1], h, l);
                *reinterpret_cast<uint32_t*>(sm + KC_A + o1) = h;
                *reinterpret_cast<uint32_t*>(sm + KC_A + 32768 + o1) = l;
                split2(xr[mi][ni][2], xr[mi][ni][3], h, l);
                *reinterpret_cast<uint32_t*>(sm + KC_A + o2) = h;
                *reinterpret_cast<uint32_t*>(sm + KC_A + 32768 + o2) = l;
            }
        cpa_wait<0>();
        __syncthreads();
        float o[4][4][4];
#pragma unroll
        for (int mi = 0; mi < 4; ++mi)
#pragma unroll
            for (int ni = 0; ni < 4; ++ni)
#pragma unroll
                for (int e = 0; e < 4; ++e) o[mi][ni][e] = 0.f;
        mma_nt(o, smb + KC_A, smb + KC_A + 32768, smb + KC_B0, smb + KC_B1, warp_m, warp_n, lane);
        float* dst = outp + base;
#pragma unroll
        for (int mi = 0; mi < 4; ++mi)
#pragma unroll
            for (int ni = 0; ni < 4; ++ni) {
                int r1 = row0 + mi * 16, col = col0 + ni * 8;
                *reinterpret_cast<float2*>(dst + r1 * 128 + col) =
                    make_float2(o[mi][ni][0] + outbs[col], o[mi][ni][1] + outbs[col + 1]);
                *reinterpret_cast<float2*>(dst + (r1 + 8) * 128 + col) =
                    make_float2(o[mi][ni][2] + outbs[col], o[mi][ni][3] + outbs[col + 1]);
            }
    }
}

// ============================ host launcher ============================
extern "C" void kernel_launch(void* const* d_in, const int* in_sizes, int n_in,
                              void* d_out, int out_size) {
    (void)in_sizes; (void)n_in; (void)out_size;
    const float* x    = (const float*)d_in[0];
    const float* Kw   = (const float*)d_in[1];
    const float* Qw   = (const float*)d_in[2];
    const float* Vw   = (const float*)d_in[3];
    const float* ln1g = (const float*)d_in[4];
    const float* ln1b = (const float*)d_in[5];
    const float* ln2g = (const float*)d_in[6];
    const float* ln2b = (const float*)d_in[7];
    const float* w1   = (const float*)d_in[8];
    const float* b1   = (const float*)d_in[9];
    const float* w2   = (const float*)d_in[10];
    const float* b2   = (const float*)d_in[11];
    const float* outw = (const float*)d_in[12];
    const float* outb = (const float*)d_in[13];
    float* out = (float*)d_out;

    cudaFuncSetAttribute(kc_mma, cudaFuncAttributeMaxDynamicSharedMemorySize, KC_SMEM);
    cudaFuncSetAttribute(kgram0, cudaFuncAttributeMaxDynamicSharedMemorySize, KG_SMEM);
    cudaFuncSetAttribute(kqk_kernel, cudaFuncAttributeMaxDynamicSharedMemorySize, TS_SMEM);
    cudaFuncSetAttribute(kgm_kernel, cudaFuncAttributeMaxDynamicSharedMemorySize, TS_SMEM);

    kprep_kernel<<<576, 256>>>(w1, w2, outw);
    kqk_kernel<<<32, 256, TS_SMEM>>>(Qw, Kw);         // QK = Qw @ Kw^T
    kgram0<<<NTILESm, 256, KG_SMEM>>>(x, ln1g, ln1b);

    for (int t = 0; t < 4; ++t) {
        int srcIsG = (t != 0);
        kgm_kernel<<<148, 256, TS_SMEM>>>(Vw);        // reduce + T1 + Mt (one launch)
        kc_mma<<<NTILESm, 256, KC_SMEM>>>(x, srcIsG, ln1g, ln1b, ln2g, ln2b,
                                          b1, b2, outb, out, t == 3);
    }
}

// round 14
// speedup vs baseline: 1.0091x; 1.0091x over previous
#include <cuda_runtime.h>
#include <cuda_bf16.h>
#include <cstdint>

#define EPSm   1e-5f
#define NROWSm 131072
#define NTILESm 1024
#define NPART  1024

// ---------------- device scratch ----------------
__device__ float g_x[NROWSm * 128];
__device__ float g_part[NPART * 128 * 128];   // 64 MB gram partials (stage 0)
__device__ float g_part2[8 * 128 * 128];      // 512 KB (stage 1)
__device__ float g_QK[128 * 128];
__device__ float g_T1[128 * 128];
__device__ unsigned g_bar1;                   // device barrier (148 arrivals/step)
__device__ unsigned g_bar2;                   // worker barrier (32 arrivals/step)
__device__ __nv_bfloat16 g_Mt_hi[128 * 128],  g_Mt_lo[128 * 128];
__device__ __nv_bfloat16 g_w1t_hi[512 * 128], g_w1t_lo[512 * 128];   // [512 n][128 k]
__device__ __nv_bfloat16 g_w2t_hi[128 * 512], g_w2t_lo[128 * 512];   // [128 n][512 k]
__device__ __nv_bfloat16 g_owt_hi[128 * 128], g_owt_lo[128 * 128];

// ---------------- helpers ----------------
__device__ __forceinline__ uint32_t smem_u32(const void* p) {
    uint32_t a;
    asm("{ .reg .u64 t; cvta.to.shared.u64 t, %1; cvt.u32.u64 %0, t; }" : "=r"(a) : "l"(p));
    return a;
}
// XOR-swizzled tile, 256B rows (128 bf16 cols)
__device__ __forceinline__ uint32_t sw16(int r, int c8) {
    return (uint32_t)(r * 256 + ((c8 ^ (r & 7)) << 4));
}
__device__ __forceinline__ uint32_t sw4(int r, int col) {
    return (uint32_t)(r * 256 + ((((col >> 3) ^ (r & 7)) << 4)) + (col & 7) * 2);
}
// XOR-swizzled tile, 128B rows (64 bf16 cols)
__device__ __forceinline__ uint32_t sw16_64(int r, int c8) {
    return (uint32_t)(r * 128 + ((((c8 ^ (r & 7)) & 7) << 4)));
}
__device__ __forceinline__ uint32_t sw4_64(int r, int col) {
    return (uint32_t)(r * 128 + ((((col >> 3) ^ (r & 7)) & 7) << 4) + (col & 7) * 2);
}
__device__ __forceinline__ void split2(float f0, float f1, uint32_t& hi, uint32_t& lo) {
    __nv_bfloat162 H = __floats2bfloat162_rn(f0, f1);
    float r0 = f0 - __bfloat162float(H.x);
    float r1 = f1 - __bfloat162float(H.y);
    __nv_bfloat162 L = __floats2bfloat162_rn(r0, r1);
    hi = *reinterpret_cast<uint32_t*>(&H);
    lo = *reinterpret_cast<uint32_t*>(&L);
}
__device__ __forceinline__ void sp1(float v, __nv_bfloat16* h, __nv_bfloat16* l) {
    __nv_bfloat16 hh = __float2bfloat16(v);
    *h = hh;
    *l = __float2bfloat16(v - __bfloat162float(hh));
}
__device__ __forceinline__ void ldsm4(uint32_t* r, uint32_t a) {
    asm volatile("ldmatrix.sync.aligned.m8n8.x4.shared.b16 {%0,%1,%2,%3}, [%4];"
                 : "=r"(r[0]), "=r"(r[1]), "=r"(r[2]), "=r"(r[3]) : "r"(a));
}
__device__ __forceinline__ void ldsm2(uint32_t* r, uint32_t a) {
    asm volatile("ldmatrix.sync.aligned.m8n8.x2.shared.b16 {%0,%1}, [%2];"
                 : "=r"(r[0]), "=r"(r[1]) : "r"(a));
}
__device__ __forceinline__ void ldsm4t(uint32_t* r, uint32_t a) {
    asm volatile("ldmatrix.sync.aligned.m8n8.x4.trans.shared.b16 {%0,%1,%2,%3}, [%4];"
                 : "=r"(r[0]), "=r"(r[1]), "=r"(r[2]), "=r"(r[3]) : "r"(a));
}
__device__ __forceinline__ void ldsm2t(uint32_t* r, uint32_t a) {
    asm volatile("ldmatrix.sync.aligned.m8n8.x2.trans.shared.b16 {%0,%1}, [%2];"
                 : "=r"(r[0]), "=r"(r[1]) : "r"(a));
}
__device__ __forceinline__ void mma_bf16(float* c, const uint32_t* a, const uint32_t* b) {
    asm volatile(
        "mma.sync.aligned.m16n8k16.row.col.f32.bf16.bf16.f32 "
        "{%0,%1,%2,%3}, {%4,%5,%6,%7}, {%8,%9}, {%0,%1,%2,%3};"
        : "+f"(c[0]), "+f"(c[1]), "+f"(c[2]), "+f"(c[3])
        : "r"(a[0]), "r"(a[1]), "r"(a[2]), "r"(a[3]), "r"(b[0]), "r"(b[1]));
}
// ---- cp.async ----
__device__ __forceinline__ void cpa16(uint32_t dst, const void* src) {
    asm volatile("cp.async.cg.shared.global [%0], [%1], 16;" :: "r"(dst), "l"(src));
}
__device__ __forceinline__ void cpa_commit() { asm volatile("cp.async.commit_group;"); }
template<int N> __device__ __forceinline__ void cpa_wait() {
    asm volatile("cp.async.wait_group %0;" :: "n"(N));
}
// nrows x 256B swizzled tile via cp.async (256 threads)
__device__ __forceinline__ void cp_tile256(uint32_t dst, const uint4* __restrict__ src,
                                           int nrows, int rs_u4, int tid) {
    int n = nrows * 16;
    for (int idx = tid; idx < n; idx += 256) {
        int r = idx >> 4, c8 = idx & 15;
        cpa16(dst + sw16(r, c8), src + r * rs_u4 + c8);
    }
}
// 128 rows x 128B swizzled tile via cp.async
__device__ __forceinline__ void cp_tile128(uint32_t dst, const uint4* __restrict__ src,
                                           int rs_u4, int tid) {
#pragma unroll
    for (int i = 0; i < 4; ++i) {
        int idx = tid + i * 256;
        int r = idx >> 3, c8 = idx & 7;
        cpa16(dst + sw16_64(r, c8), src + r * rs_u4 + c8);
    }
}

// C[128][128] += A(128x128k) @ Bt(128n x 128k)^T, bf16 3-split (256B-row tiles)
__device__ __forceinline__ void mma_nt(float (&acc)[4][4][4],
                                       uint32_t aHi, uint32_t aLo,
                                       uint32_t bHi, uint32_t bLo,
                                       int warp_m, int warp_n, int lane) {
#pragma unroll
    for (int k8 = 0; k8 < 8; ++k8) {
        uint32_t aH[4][4], aL[4][4], bH[4][2], bL[4][2];
        int ar = warp_m * 64 + (lane & 15);
        int ac8 = k8 * 2 + (lane >> 4);
#pragma unroll
        for (int mi = 0; mi < 4; ++mi) {
            uint32_t off = sw16(ar + mi * 16, ac8);
            ldsm4(aH[mi], aHi + off);
            ldsm4(aL[mi], aLo + off);
        }
        int l15 = lane & 15;
        int br = warp_n * 32 + (l15 & 7);
        int bc8 = k8 * 2 + (l15 >> 3);
#pragma unroll
        for (int ni = 0; ni < 4; ++ni) {
            uint32_t off = sw16(br + ni * 8, bc8);
            ldsm2(bH[ni], bHi + off);
            ldsm2(bL[ni], bLo + off);
        }
#pragma unroll
        for (int mi = 0; mi < 4; ++mi)
#pragma unroll
            for (int ni = 0; ni < 4; ++ni) {
                mma_bf16(acc[mi][ni], aH[mi], bH[ni]);
                mma_bf16(acc[mi][ni], aH[mi], bL[ni]);
                mma_bf16(acc[mi][ni], aL[mi], bH[ni]);
            }
    }
}

// u[128][64] = A(128x128k) @ Bt(64n x 128k)^T  (B tile 64 rows, 256B rows)
__device__ __forceinline__ void mma_n64(float (&u)[4][2][4],
                                        uint32_t aHi, uint32_t aLo,
                                        uint32_t bHi, uint32_t bLo,
                                        int warp_m, int warp_n, int lane) {
#pragma unroll
    for (int k8 = 0; k8 < 8; ++k8) {
        uint32_t aH[4][4], aL[4][4], bH[2][2], bL[2][2];
        int ar = warp_m * 64 + (lane & 15);
        int ac8 = k8 * 2 + (lane >> 4);
#pragma unroll
        for (int mi = 0; mi < 4; ++mi) {
            uint32_t off = sw16(ar + mi * 16, ac8);
            ldsm4(aH[mi], aHi + off);
            ldsm4(aL[mi], aLo + off);
        }
        int l15 = lane & 15;
        int br = warp_n * 16 + (l15 & 7);
        int bc8 = k8 * 2 + (l15 >> 3);
#pragma unroll
        for (int ni = 0; ni < 2; ++ni) {
            uint32_t off = sw16(br + ni * 8, bc8);
            ldsm2(bH[ni], bHi + off);
            ldsm2(bL[ni], bLo + off);
        }
#pragma unroll
        for (int mi = 0; mi < 4; ++mi)
#pragma unroll
            for (int ni = 0; ni < 2; ++ni) {
                mma_bf16(u[mi][ni], aH[mi], bH[ni]);
                mma_bf16(u[mi][ni], aH[mi], bL[ni]);
                mma_bf16(u[mi][ni], aL[mi], bH[ni]);
            }
    }
}

// C[128][128] += F(128m x 64k) @ Bt(128n x 64k)^T  (128B-row tiles)
__device__ __forceinline__ void mma_k64(float (&acc)[4][4][4],
                                        uint32_t fHi, uint32_t fLo,
                                        uint32_t bHi, uint32_t bLo,
                                        int warp_m, int warp_n, int lane) {
#pragma unroll
    for (int k8 = 0; k8 < 4; ++k8) {
        uint32_t aH[4][4], aL[4][4], bH[4][2], bL[4][2];
        int ar = warp_m * 64 + (lane & 15);
        int ac8 = k8 * 2 + (lane >> 4);
#pragma unroll
        for (int mi = 0; mi < 4; ++mi) {
            uint32_t off = sw16_64(ar + mi * 16, ac8);
            ldsm4(aH[mi], fHi + off);
            ldsm4(aL[mi], fLo + off);
        }
        int l15 = lane & 15;
        int br = warp_n * 32 + (l15 & 7);
        int bc8 = k8 * 2 + (l15 >> 3);
#pragma unroll
        for (int ni = 0; ni < 4; ++ni) {
            uint32_t off = sw16_64(br + ni * 8, bc8);
            ldsm2(bH[ni], bHi + off);
            ldsm2(bL[ni], bLo + off);
        }
#pragma unroll
        for (int mi = 0; mi < 4; ++mi)
#pragma unroll
            for (int ni = 0; ni < 4; ++ni) {
                mma_bf16(acc[mi][ni], aH[mi], bH[ni]);
                mma_bf16(acc[mi][ni], aH[mi], bL[ni]);
                mma_bf16(acc[mi][ni], aL[mi], bH[ni]);
            }
    }
}

// Gram: C += H^T @ H, bf16 3-split; trans loads of row-major H tile.
__device__ __forceinline__ void mma_tt(float (&acc)[4][4][4],
                                       uint32_t hHi, uint32_t hLo,
                                       int warp_m, int warp_n, int lane) {
#pragma unroll
    for (int k8 = 0; k8 < 8; ++k8) {
        int k0 = k8 * 16;
        uint32_t aH[4][4], aL[4][4], bH[4][2], bL[4][2];
        int ar = k0 + (lane & 7) + ((lane >> 4) << 3);
        int asel = (lane >> 3) & 1;
#pragma unroll
        for (int mi = 0; mi < 4; ++mi) {
            int c8 = ((warp_m * 64 + mi * 16) >> 3) + asel;
            uint32_t off = sw16(ar, c8);
            ldsm4t(aH[mi], hHi + off);
            ldsm4t(aL[mi], hLo + off);
        }
        int l15 = lane & 15;
        int br = k0 + (l15 & 7) + ((l15 >> 3) << 3);
#pragma unroll
        for (int ni = 0; ni < 4; ++ni) {
            int c8 = (warp_n * 32 + ni * 8) >> 3;
            uint32_t off = sw16(br, c8);
            ldsm2t(bH[ni], hHi + off);
            ldsm2t(bL[ni], hLo + off);
        }
#pragma unroll
        for (int mi = 0; mi < 4; ++mi)
#pragma unroll
            for (int ni = 0; ni < 4; ++ni) {
                mma_bf16(acc[mi][ni], aH[mi], bH[ni]);
                mma_bf16(acc[mi][ni], aH[mi], bL[ni]);
                mma_bf16(acc[mi][ni], aL[mi], bH[ni]);
            }
    }
}

// LayerNorm of fragment-layout values -> split hi/lo into swizzled 256B-row tile.
template<bool ENDSYNC>
__device__ __forceinline__ void ln_acc(const float (&v)[4][4][4],
                                       const float* gs, const float* bs,
                                       char* Ahi, char* Alo,
                                       float2* red,
                                       int warp_m, int warp_n, int lane, int tid) {
    int row0 = warp_m * 64 + (lane >> 2);
    int col0 = warp_n * 32 + (lane & 3) * 2;
#pragma unroll
    for (int mi = 0; mi < 4; ++mi) {
        float s1 = 0, q1 = 0, s2 = 0, q2 = 0;
#pragma unroll
        for (int ni = 0; ni < 4; ++ni) {
            s1 += v[mi][ni][0] + v[mi][ni][1];
            q1 += v[mi][ni][0] * v[mi][ni][0] + v[mi][ni][1] * v[mi][ni][1];
            s2 += v[mi][ni][2] + v[mi][ni][3];
            q2 += v[mi][ni][2] * v[mi][ni][2] + v[mi][ni][3] * v[mi][ni][3];
        }
        s1 += __shfl_xor_sync(~0u, s1, 1); s1 += __shfl_xor_sync(~0u, s1, 2);
        q1 += __shfl_xor_sync(~0u, q1, 1); q1 += __shfl_xor_sync(~0u, q1, 2);
        s2 += __shfl_xor_sync(~0u, s2, 1); s2 += __shfl_xor_sync(~0u, s2, 2);
        q2 += __shfl_xor_sync(~0u, q2, 1); q2 += __shfl_xor_sync(~0u, q2, 2);
        if ((lane & 3) == 0) {
            int r1 = row0 + mi * 16;
            red[r1 * 4 + warp_n] = make_float2(s1, q1);
            red[(r1 + 8) * 4 + warp_n] = make_float2(s2, q2);
        }
    }
    __syncthreads();
#pragma unroll
    for (int mi = 0; mi < 4; ++mi) {
        int r1 = row0 + mi * 16;
        float s1 = 0, q1 = 0, s2 = 0, q2 = 0;
#pragma unroll
        for (int w = 0; w < 4; ++w) {
            float2 p1 = red[r1 * 4 + w];
            float2 p2 = red[(r1 + 8) * 4 + w];
            s1 += p1.x; q1 += p1.y;
            s2 += p2.x; q2 += p2.y;
        }
        float m1 = s1 * (1.0f / 128.0f);
        float rs1 = rsqrtf(q1 * (1.0f / 128.0f) - m1 * m1 + EPSm);
        float m2 = s2 * (1.0f / 128.0f);
        float rs2 = rsqrtf(q2 * (1.0f / 128.0f) - m2 * m2 + EPSm);
#pragma unroll
        for (int ni = 0; ni < 4; ++ni) {
            int col = col0 + ni * 8;
            float g0 = gs[col], g1 = gs[col + 1], bb0 = bs[col], bb1 = bs[col + 1];
            int r2 = r1 + 8;
            float f0 = (v[mi][ni][0] - m1) * rs1 * g0 + bb0;
            float f1 = (v[mi][ni][1] - m1) * rs1 * g1 + bb1;
            float f2 = (v[mi][ni][2] - m2) * rs2 * g0 + bb0;
            float f3 = (v[mi][ni][3] - m2) * rs2 * g1 + bb1;
            uint32_t h, l;
            uint32_t o1 = sw4(r1, col), o2 = sw4(r2, col);
            split2(f0, f1, h, l);
            *reinterpret_cast<uint32_t*>(Ahi + o1) = h;
            *reinterpret_cast<uint32_t*>(Alo + o1) = l;
            split2(f2, f3, h, l);
            *reinterpret_cast<uint32_t*>(Ahi + o2) = h;
            *reinterpret_cast<uint32_t*>(Alo + o2) = l;
        }
    }
    if (ENDSYNC) __syncthreads();
}

// ============================ kernels ============================

__global__ void kprep_kernel(const float* __restrict__ w1, const float* __restrict__ w2,
                             const float* __restrict__ outw) {
    int idx = blockIdx.x * 256 + threadIdx.x;
    if (idx < 65536) {                 // w1t [512 n][128 k]
        int n = idx >> 7, k = idx & 127;
        sp1(w1[k * 512 + n], &g_w1t_hi[idx], &g_w1t_lo[idx]);
    } else if (idx < 131072) {         // w2t [128 n][512 k]
        int j = idx - 65536;
        int n = j >> 9, k = j & 511;
        sp1(w2[k * 128 + n], &g_w2t_hi[j], &g_w2t_lo[j]);
    } else if (idx < 147456) {         // owt [128 n][128 k]
        int j = idx - 131072;
        int n = j >> 7, k = j & 127;
        sp1(outw[k * 128 + n], &g_owt_hi[j], &g_owt_lo[j]);
    }
}

// t=0 Gram partials: one 128-row tile per CTA; h = LN1(x); part = h^T h.
#define KG_SMEM (6144 + 65536)
__global__ void __launch_bounds__(256, 1)
kgram0(const float* __restrict__ xin,
       const float* __restrict__ lng, const float* __restrict__ lnb) {
    extern __shared__ char sm[];
    float* gs = reinterpret_cast<float*>(sm);
    float* bs = gs + 128;
    float2* red = reinterpret_cast<float2*>(sm + 1024);
    char* Hhi = sm + 6144;
    char* Hlo = sm + 6144 + 32768;
    uint32_t smb = smem_u32(sm);
    int tid = threadIdx.x, lane = tid & 31, wid = tid >> 5;
    int warp_m = wid & 1, warp_n = wid >> 1;
    int row0 = warp_m * 64 + (lane >> 2);
    int col0 = warp_n * 32 + (lane & 3) * 2;
    if (tid < 128) { gs[tid] = lng[tid]; bs[tid] = lnb[tid]; }
    __syncthreads();

    const float* xt = xin + (size_t)blockIdx.x * 16384;
    float v[4][4][4];
#pragma unroll
    for (int mi = 0; mi < 4; ++mi)
#pragma unroll
        for (int ni = 0; ni < 4; ++ni) {
            const float* p = xt + (row0 + mi * 16) * 128 + col0 + ni * 8;
            float2 a = *reinterpret_cast<const float2*>(p);
            float2 b = *reinterpret_cast<const float2*>(p + 8 * 128);
            v[mi][ni][0] = a.x; v[mi][ni][1] = a.y;
            v[mi][ni][2] = b.x; v[mi][ni][3] = b.y;
        }
    ln_acc<true>(v, gs, bs, Hhi, Hlo, red, warp_m, warp_n, lane, tid);

    float acc[4][4][4];
#pragma unroll
    for (int mi = 0; mi < 4; ++mi)
#pragma unroll
        for (int ni = 0; ni < 4; ++ni)
#pragma unroll
            for (int e = 0; e < 4; ++e) acc[mi][ni][e] = 0.f;
    mma_tt(acc, smb + 6144, smb + 6144 + 32768, warp_m, warp_n, lane);

    float* dst = g_part + (size_t)blockIdx.x * 16384;
#pragma unroll
    for (int mi = 0; mi < 4; ++mi)
#pragma unroll
        for (int ni = 0; ni < 4; ++ni) {
            int r1 = row0 + mi * 16, col = col0 + ni * 8;
            __stcs(reinterpret_cast<float2*>(dst + r1 * 128 + col),
                   make_float2(acc[mi][ni][0], acc[mi][ni][1]));
            __stcs(reinterpret_cast<float2*>(dst + (r1 + 8) * 128 + col),
                   make_float2(acc[mi][ni][2], acc[mi][ni][3]));
        }
}

// one-shot QK = Qw @ Kw^T (launch-time prep)
#define TS_SMEM (128 * 129 * 4 + 512 * 4)
__global__ void __launch_bounds__(256, 1)
kqk_kernel(const float* __restrict__ A, const float* __restrict__ B) {
    extern __shared__ float ts[];
    float* Bs = ts;
    float* As = ts + 128 * 129;
    int tid = threadIdx.x;
    for (int idx = tid; idx < 16384; idx += 256)
        Bs[(idx >> 7) * 129 + (idx & 127)] = B[idx];
    int r0 = blockIdx.x * 4;
    for (int idx = tid; idx < 512; idx += 256)
        As[idx] = A[(r0 + (idx >> 7)) * 128 + (idx & 127)];
    __syncthreads();
    int j = tid & 127, i0 = (tid >> 7) * 2;
    float c0 = 0.f, c1 = 0.f;
#pragma unroll 8
    for (int k = 0; k < 128; ++k) {
        float b = Bs[j * 129 + k];
        c0 = fmaf(As[i0 * 128 + k], b, c0);
        c1 = fmaf(As[i0 * 128 + 128 + k], b, c1);
    }
    g_QK[(r0 + i0) * 128 + j] = c0;
    g_QK[(r0 + i0 + 1) * 128 + j] = c1;
}

// ===== fused per-step reduce + mid kernel (persistent, 148 CTAs x 1024 thr) =====
// Phase A (all threads, one job each): reduce 1024 partials -> 8 slabs.
// Device barrier #1. Phase B (CTAs 0..31): T1 = G @ Vw. Worker barrier #2.
// Phase C: Mt = split(QK @ T1).
__global__ void __launch_bounds__(1024, 1)
kgm_kernel(const float* __restrict__ Vw) {
    extern __shared__ float ts[];
    float* Bs = ts;                 // [128][129]
    float* As = ts + 128 * 129;     // [4][128]
    int tid = threadIdx.x;
    int cta = blockIdx.x;
    bool worker = (cta < 32);

    // ---- phase A: 151552 threads cover 131072 jobs; each sums 128 partials
    {
        int job = cta * 1024 + tid;
        if (job < 131072) {
            int e = job & 16383;
            int g = job >> 14;                      // 0..7
            const float* p = g_part + (size_t)g * 128 * 16384 + e;
            float s0 = 0.f, s1 = 0.f, s2 = 0.f, s3 = 0.f;
#pragma unroll 8
            for (int i = 0; i < 128; i += 4) {
                s0 += __ldcs(p + (size_t)(i + 0) * 16384);
                s1 += __ldcs(p + (size_t)(i + 1) * 16384);
                s2 += __ldcs(p + (size_t)(i + 2) * 16384);
                s3 += __ldcs(p + (size_t)(i + 3) * 16384);
            }
            g_part2[(size_t)g * 16384 + e] = (s0 + s1) + (s2 + s3);
        }
    }
    // workers preload Vw into Bs (overlaps other CTAs' phase A)
    if (worker) {
        for (int idx = tid; idx < 16384; idx += 1024)
            Bs[(idx >> 7) * 129 + (idx & 127)] = Vw[idx];
    }
    // ---- device barrier #1 (148 arrivals; non-workers arrive and exit)
    __threadfence();
    __syncthreads();
    if (!worker) {
        if (tid == 0) atomicAdd(&g_bar1, 1u);
        return;
    }
    if (tid == 0) {
        unsigned arrive = atomicAdd(&g_bar1, 1u);
        unsigned target = (arrive / 148u + 1u) * 148u;
        while (*reinterpret_cast<volatile unsigned*>(&g_bar1) < target)
            __nanosleep(64);
        __threadfence();
    }
    __syncthreads();

    // ---- phase B: T1 = G @ Vw  (G rows summed from 8 slabs)
    int r0 = cta * 4;
    if (tid < 512) {
        int off = (r0 + (tid >> 7)) * 128 + (tid & 127);
        const float* p = g_part2 + off;
        float s = 0.f;
#pragma unroll
        for (int g = 0; g < 8; ++g) s += p[(size_t)g * 16384];
        As[tid] = s;
    }
    __syncthreads();
    if (tid < 512) {
        int j = tid & 127, i = tid >> 7;     // i = 0..3
        float c = 0.f;
#pragma unroll 8
        for (int k = 0; k < 128; ++k)
            c = fmaf(As[i * 128 + k], Bs[k * 129 + j], c);
        g_T1[(r0 + i) * 128 + j] = c;
    }
    // ---- worker barrier #2 (32 arrivals)
    __threadfence();
    __syncthreads();
    if (tid == 0) {
        unsigned arrive = atomicAdd(&g_bar2, 1u);
        unsigned target = (arrive / 32u + 1u) * 32u;
        while (*reinterpret_cast<volatile unsigned*>(&g_bar2) < target)
            __nanosleep(64);
        __threadfence();
    }
    __syncthreads();
    // ---- phase C: Mt = split(QK @ T1)
    for (int idx = tid; idx < 16384; idx += 1024)
        Bs[(idx >> 7) * 129 + (idx & 127)] = __ldcg(g_T1 + idx);
    if (tid < 512)
        As[tid] = g_QK[(r0 + (tid >> 7)) * 128 + (tid & 127)];
    __syncthreads();
    if (tid < 512) {
        int j = tid & 127, i = tid >> 7;
        float c = 0.f;
#pragma unroll 8
        for (int k = 0; k < 128; ++k)
            c = fmaf(As[i * 128 + k], Bs[k * 129 + j], c);
        sp1(c, &g_Mt_hi[j * 128 + r0 + i], &g_Mt_lo[j * 128 + r0 + i]);
    }
}

// ================= big fused kernel (HMMA + cp.async, 2-sync FF pipeline) =================
#define KC_RED  5120
#define KC_A    10240                  // Ahi 32K | Alo 32K
#define KC_B0   (KC_A + 65536)         // 32K (hi at +0, lo at +16384 for FF tiles)
#define KC_B1   (KC_B0 + 32768)
#define KC_F    (KC_B1 + 32768)        // Fhi 16K | Flo 16K
#define KC_SMEM (KC_F + 32768)         // 174080

__global__ void __launch_bounds__(256, 1)
kc_mma(const float* __restrict__ xin, int srcIsG,
       const float* __restrict__ ln1g, const float* __restrict__ ln1b,
       const float* __restrict__ ln2g, const float* __restrict__ ln2b,
       const float* __restrict__ b1, const float* __restrict__ b2,
       const float* __restrict__ outb, float* __restrict__ outp, int last) {
    extern __shared__ char sm[];
    uint32_t smb = smem_u32(sm);
    int tid = threadIdx.x, lane = tid & 31, wid = tid >> 5;
    int warp_m = wid & 1, warp_n = wid >> 1;
    int row0 = warp_m * 64 + (lane >> 2);
    int col0 = warp_n * 32 + (lane & 3) * 2;

    float* ln1gs = reinterpret_cast<float*>(sm);
    float* ln1bs = ln1gs + 128;
    float* ln2gs = ln1gs + 256;
    float* ln2bs = ln1gs + 384;
    float* b2s   = ln1gs + 512;
    float* outbs = ln1gs + 640;
    float* b1s   = ln1gs + 768;     // 512 floats
    float2* red  = reinterpret_cast<float2*>(sm + KC_RED);
    if (tid < 128) {
        ln1gs[tid] = ln1g[tid]; ln1bs[tid] = ln1b[tid];
        ln2gs[tid] = ln2g[tid]; ln2bs[tid] = ln2b[tid];
        b2s[tid] = b2[tid]; outbs[tid] = outb[tid];
    }
    b1s[tid] = b1[tid]; b1s[tid + 256] = b1[tid + 256];

    // prefetch Mt (hi -> B0, lo -> B1), overlapped with x load + LN1
    cp_tile256(smb + KC_B0, reinterpret_cast<const uint4*>(g_Mt_hi), 128, 16, tid);
    cp_tile256(smb + KC_B1, reinterpret_cast<const uint4*>(g_Mt_lo), 128, 16, tid);
    cpa_commit();

    // x in fragment layout
    size_t base = (size_t)blockIdx.x * 16384;
    const float* xt = (srcIsG ? g_x : xin) + base;
    float xr[4][4][4];
#pragma unroll
    for (int mi = 0; mi < 4; ++mi)
#pragma unroll
        for (int ni = 0; ni < 4; ++ni) {
            const float* p = xt + (row0 + mi * 16) * 128 + col0 + ni * 8;
            float2 a = *reinterpret_cast<const float2*>(p);
            float2 b = *reinterpret_cast<const float2*>(p + 8 * 128);
            xr[mi][ni][0] = a.x; xr[mi][ni][1] = a.y;
            xr[mi][ni][2] = b.x; xr[mi][ni][3] = b.y;
        }

    // A <- LN1(x)  (end-sync folded into the cpa_wait sync below)
    ln_acc<false>(xr, ln1gs, ln1bs, sm + KC_A, sm + KC_A + 32768, red, warp_m, warp_n, lane, tid);
    cpa_wait<0>();
    __syncthreads();
    // x += h @ M
    mma_nt(xr, smb + KC_A, smb + KC_A + 32768, smb + KC_B0, smb + KC_B1, warp_m, warp_n, lane);
    __syncthreads();

    // prime FF pipeline: w1 sub-chunk 0 -> B0
    cp_tile256(smb + KC_B0,         reinterpret_cast<const uint4*>(g_w1t_hi), 64, 16, tid);
    cp_tile256(smb + KC_B0 + 16384, reinterpret_cast<const uint4*>(g_w1t_lo), 64, 16, tid);
    cpa_commit();

    // A <- LN2(x)  (end-sync folded into the cpa_wait sync below)
    ln_acc<false>(xr, ln2gs, ln2bs, sm + KC_A, sm + KC_A + 32768, red, warp_m, warp_n, lane, tid);
    cpa_wait<0>();       // w1_0 landed
    __syncthreads();     // w1_0 + A visible

    // FF: 8 sub-chunks of 64 hidden units, double-buffered weights, 2 syncs/iter
#pragma unroll 1
    for (int c = 0; c < 8; ++c) {
        // prefetch w2_c -> B1 (overlaps mma1 + relu)
        cp_tile128(smb + KC_B1,         reinterpret_cast<const uint4*>(g_w2t_hi) + c * 8, 64, tid);
        cp_tile128(smb + KC_B1 + 16384, reinterpret_cast<const uint4*>(g_w2t_lo) + c * 8, 64, tid);
        cpa_commit();
        float u[4][2][4];
#pragma unroll
        for (int mi = 0; mi < 4; ++mi)
#pragma unroll
            for (int ni = 0; ni < 2; ++ni)
#pragma unroll
                for (int e = 0; e < 4; ++e) u[mi][ni][e] = 0.f;
        mma_n64(u, smb + KC_A, smb + KC_A + 32768, smb + KC_B0, smb + KC_B0 + 16384,
                warp_m, warp_n, lane);
        // bias + relu + split -> F
#pragma unroll
        for (int mi = 0; mi < 4; ++mi)
#pragma unroll
            for (int ni = 0; ni < 2; ++ni) {
                int hcol = warp_n * 16 + (lane & 3) * 2 + ni * 8;      // 0..63
                float bb0 = b1s[c * 64 + hcol], bb1 = b1s[c * 64 + hcol + 1];
                int r1 = row0 + mi * 16, r2 = r1 + 8;
                float f0 = fmaxf(u[mi][ni][0] + bb0, 0.f);
                float f1 = fmaxf(u[mi][ni][1] + bb1, 0.f);
                float f2 = fmaxf(u[mi][ni][2] + bb0, 0.f);
                float f3 = fmaxf(u[mi][ni][3] + bb1, 0.f);
                uint32_t h, l;
                uint32_t o1 = sw4_64(r1, hcol), o2 = sw4_64(r2, hcol);
                split2(f0, f1, h, l);
                *reinterpret_cast<uint32_t*>(sm + KC_F + o1) = h;
                *reinterpret_cast<uint32_t*>(sm + KC_F + 16384 + o1) = l;
                split2(f2, f3, h, l);
                *reinterpret_cast<uint32_t*>(sm + KC_F + o2) = h;
                *reinterpret_cast<uint32_t*>(sm + KC_F + 16384 + o2) = l;
            }
        cpa_wait<0>();       // w2_c landed
        __syncthreads();     // F + w2_c visible; B0 (w1_c) free
        // prefetch w1_{c+1} -> B0 (overlaps mma2); last iter: owt_hi if needed
        if (c < 7) {
            cp_tile256(smb + KC_B0,         reinterpret_cast<const uint4*>(g_w1t_hi) + (c + 1) * 1024, 64, 16, tid);
            cp_tile256(smb + KC_B0 + 16384, reinterpret_cast<const uint4*>(g_w1t_lo) + (c + 1) * 1024, 64, 16, tid);
        } else if (last) {
            cp_tile256(smb + KC_B0, reinterpret_cast<const uint4*>(g_owt_hi), 128, 16, tid);
        }
        cpa_commit();
        mma_k64(xr, smb + KC_F, smb + KC_F + 16384, smb + KC_B1, smb + KC_B1 + 16384,
                warp_m, warp_n, lane);
        cpa_wait<0>();       // w1_{c+1} (or owt_hi) landed
        __syncthreads();     // B1/F free; next tile visible
    }

    // + b2
#pragma unroll
    for (int mi = 0; mi < 4; ++mi)
#pragma unroll
        for (int ni = 0; ni < 4; ++ni) {
            int col = col0 + ni * 8;
            xr[mi][ni][0] += b2s[col];     xr[mi][ni][1] += b2s[col + 1];
            xr[mi][ni][2] += b2s[col];     xr[mi][ni][3] += b2s[col + 1];
        }

    if (!last) {
        // store x_new
        float* dst = g_x + base;
#pragma unroll
        for (int mi = 0; mi < 4; ++mi)
#pragma unroll
            for (int ni = 0; ni < 4; ++ni) {
                int r1 = row0 + mi * 16, col = col0 + ni * 8;
                *reinterpret_cast<float2*>(dst + r1 * 128 + col) =
                    make_float2(xr[mi][ni][0], xr[mi][ni][1]);
                *reinterpret_cast<float2*>(dst + (r1 + 8) * 128 + col) =
                    make_float2(xr[mi][ni][2], xr[mi][ni][3]);
            }
        // fused Gram partial for the NEXT step: h = LN1(x_new); part = h^T h
        ln_acc<true>(xr, ln1gs, ln1bs, sm + KC_A, sm + KC_A + 32768, red, warp_m, warp_n, lane, tid);
        float ga[4][4][4];
#pragma unroll
        for (int mi = 0; mi < 4; ++mi)
#pragma unroll
            for (int ni = 0; ni < 4; ++ni)
#pragma unroll
                for (int e = 0; e < 4; ++e) ga[mi][ni][e] = 0.f;
        mma_tt(ga, smb + KC_A, smb + KC_A + 32768, warp_m, warp_n, lane);
        float* pdst = g_part + (size_t)blockIdx.x * 16384;
#pragma unroll
        for (int mi = 0; mi < 4; ++mi)
#pragma unroll
            for (int ni = 0; ni < 4; ++ni) {
                int r1 = row0 + mi * 16, col = col0 + ni * 8;
                __stcs(reinterpret_cast<float2*>(pdst + r1 * 128 + col),
                       make_float2(ga[mi][ni][0], ga[mi][ni][1]));
                __stcs(reinterpret_cast<float2*>(pdst + (r1 + 8) * 128 + col),
                       make_float2(ga[mi][ni][2], ga[mi][ni][3]));
            }
    } else {
        // out = x @ outw + outb  (owt_hi already landed in B0 at loop end)
        cp_tile256(smb + KC_B1, reinterpret_cast<const uint4*>(g_owt_lo), 128, 16, tid);
        cpa_commit();
        // split x -> A
#pragma unroll
        for (int mi = 0; mi < 4; ++mi)
#pragma unroll
            for (int ni = 0; ni < 4; ++ni) {
                int col = col0 + ni * 8;
                int r1 = row0 + mi * 16, r2 = r1 + 8;
                uint32_t h, l;
                uint32_t o1 = sw4(r1, col), o2 = sw4(r2, col);
                split2(xr[mi][ni][0], xr[mi][ni][1], h, l);
                *reinterpret_cast<uint32_t*>(sm + KC_A + o1) = h;
                *reinterpret_cast<uint32_t*>(sm + KC_A + 32768 + o1) = l;
                split2(xr[mi][ni][2], xr[mi][ni][3], h, l);
                *reinterpret_cast<uint32_t*>(sm + KC_A + o2) = h;
                *reinterpret_cast<uint32_t*>(sm + KC_A + 32768 + o2) = l;
            }
        cpa_wait<0>();
        __syncthreads();
        float o[4][4][4];
#pragma unroll
        for (int mi = 0; mi < 4; ++mi)
#pragma unroll
            for (int ni = 0; ni < 4; ++ni)
#pragma unroll
                for (int e = 0; e < 4; ++e) o[mi][ni][e] = 0.f;
        mma_nt(o, smb + KC_A, smb + KC_A + 32768, smb + KC_B0, smb + KC_B1, warp_m, warp_n, lane);
        float* dst = outp + base;
#pragma unroll
        for (int mi = 0; mi < 4; ++mi)
#pragma unroll
            for (int ni = 0; ni < 4; ++ni) {
                int r1 = row0 + mi * 16, col = col0 + ni * 8;
                *reinterpret_cast<float2*>(dst + r1 * 128 + col) =
                    make_float2(o[mi][ni][0] + outbs[col], o[mi][ni][1] + outbs[col + 1]);
                *reinterpret_cast<float2*>(dst + (r1 + 8) * 128 + col) =
                    make_float2(o[mi][ni][2] + outbs[col], o[mi][ni][3] + outbs[col + 1]);
            }
    }
}

// ============================ host launcher ============================
extern "C" void kernel_launch(void* const* d_in, const int* in_sizes, int n_in,
                              void* d_out, int out_size) {
    (void)in_sizes; (void)n_in; (void)out_size;
    const float* x    = (const float*)d_in[0];
    const float* Kw   = (const float*)d_in[1];
    const float* Qw   = (const float*)d_in[2];
    const float* Vw   = (const float*)d_in[3];
    const float* ln1g = (const float*)d_in[4];
    const float* ln1b = (const float*)d_in[5];
    const float* ln2g = (const float*)d_in[6];
    const float* ln2b = (const float*)d_in[7];
    const float* w1   = (const float*)d_in[8];
    const float* b1   = (const float*)d_in[9];
    const float* w2   = (const float*)d_in[10];
    const float* b2   = (const float*)d_in[11];
    const float* outw = (const float*)d_in[12];
    const float* outb = (const float*)d_in[13];
    float* out = (float*)d_out;

    cudaFuncSetAttribute(kc_mma, cudaFuncAttributeMaxDynamicSharedMemorySize, KC_SMEM);
    cudaFuncSetAttribute(kgram0, cudaFuncAttributeMaxDynamicSharedMemorySize, KG_SMEM);
    cudaFuncSetAttribute(kqk_kernel, cudaFuncAttributeMaxDynamicSharedMemorySize, TS_SMEM);
    cudaFuncSetAttribute(kgm_kernel, cudaFuncAttributeMaxDynamicSharedMemorySize, TS_SMEM);

    kprep_kernel<<<576, 256>>>(w1, w2, outw);
    kqk_kernel<<<32, 256, TS_SMEM>>>(Qw, Kw);         // QK = Qw @ Kw^T
    kgram0<<<NTILESm, 256, KG_SMEM>>>(x, ln1g, ln1b);

    for (int t = 0; t < 4; ++t) {
        int srcIsG = (t != 0);
        kgm_kernel<<<148, 1024, TS_SMEM>>>(Vw);       // reduce + T1 + Mt (one launch)
        kc_mma<<<NTILESm, 256, KC_SMEM>>>(x, srcIsG, ln1g, ln1b, ln2g, ln2b,
                                          b1, b2, outb, out, t == 3);
    }
}

// round 15
// speedup vs baseline: 1.0141x; 1.0049x over previous
#include <cuda_runtime.h>
#include <cuda_bf16.h>
#include <cstdint>

#define EPSm   1e-5f
#define NROWSm 131072
#define NTILESm 1024
#define NPART  1024

// ---------------- device scratch ----------------
__device__ float g_x[NROWSm * 128];
__device__ float g_part[NPART * 128 * 128];   // 64 MB gram partials (stage 0)
__device__ float g_part2[8 * 128 * 128];      // 512 KB (stage 1)
__device__ float g_QK[128 * 128];
__device__ float g_T1[128 * 128];
__device__ unsigned g_barrier;                // monotonic ticket barrier for kmid
__device__ __nv_bfloat16 g_Mt_hi[128 * 128],  g_Mt_lo[128 * 128];
__device__ __nv_bfloat16 g_w1t_hi[512 * 128], g_w1t_lo[512 * 128];   // [512 n][128 k]
__device__ __nv_bfloat16 g_w2t_hi[128 * 512], g_w2t_lo[128 * 512];   // [128 n][512 k]
__device__ __nv_bfloat16 g_owt_hi[128 * 128], g_owt_lo[128 * 128];

// ---------------- helpers ----------------
__device__ __forceinline__ uint32_t smem_u32(const void* p) {
    uint32_t a;
    asm("{ .reg .u64 t; cvta.to.shared.u64 t, %1; cvt.u32.u64 %0, t; }" : "=r"(a) : "l"(p));
    return a;
}
// XOR-swizzled tile, 256B rows (128 bf16 cols)
__device__ __forceinline__ uint32_t sw16(int r, int c8) {
    return (uint32_t)(r * 256 + ((c8 ^ (r & 7)) << 4));
}
__device__ __forceinline__ uint32_t sw4(int r, int col) {
    return (uint32_t)(r * 256 + ((((col >> 3) ^ (r & 7)) << 4)) + (col & 7) * 2);
}
// XOR-swizzled tile, 128B rows (64 bf16 cols)
__device__ __forceinline__ uint32_t sw16_64(int r, int c8) {
    return (uint32_t)(r * 128 + ((((c8 ^ (r & 7)) & 7) << 4)));
}
__device__ __forceinline__ uint32_t sw4_64(int r, int col) {
    return (uint32_t)(r * 128 + ((((col >> 3) ^ (r & 7)) & 7) << 4) + (col & 7) * 2);
}
__device__ __forceinline__ void split2(float f0, float f1, uint32_t& hi, uint32_t& lo) {
    __nv_bfloat162 H = __floats2bfloat162_rn(f0, f1);
    float r0 = f0 - __bfloat162float(H.x);
    float r1 = f1 - __bfloat162float(H.y);
    __nv_bfloat162 L = __floats2bfloat162_rn(r0, r1);
    hi = *reinterpret_cast<uint32_t*>(&H);
    lo = *reinterpret_cast<uint32_t*>(&L);
}
__device__ __forceinline__ void sp1(float v, __nv_bfloat16* h, __nv_bfloat16* l) {
    __nv_bfloat16 hh = __float2bfloat16(v);
    *h = hh;
    *l = __float2bfloat16(v - __bfloat162float(hh));
}
__device__ __forceinline__ void ldsm4(uint32_t* r, uint32_t a) {
    asm volatile("ldmatrix.sync.aligned.m8n8.x4.shared.b16 {%0,%1,%2,%3}, [%4];"
                 : "=r"(r[0]), "=r"(r[1]), "=r"(r[2]), "=r"(r[3]) : "r"(a));
}
__device__ __forceinline__ void ldsm2(uint32_t* r, uint32_t a) {
    asm volatile("ldmatrix.sync.aligned.m8n8.x2.shared.b16 {%0,%1}, [%2];"
                 : "=r"(r[0]), "=r"(r[1]) : "r"(a));
}
__device__ __forceinline__ void ldsm4t(uint32_t* r, uint32_t a) {
    asm volatile("ldmatrix.sync.aligned.m8n8.x4.trans.shared.b16 {%0,%1,%2,%3}, [%4];"
                 : "=r"(r[0]), "=r"(r[1]), "=r"(r[2]), "=r"(r[3]) : "r"(a));
}
__device__ __forceinline__ void ldsm2t(uint32_t* r, uint32_t a) {
    asm volatile("ldmatrix.sync.aligned.m8n8.x2.trans.shared.b16 {%0,%1}, [%2];"
                 : "=r"(r[0]), "=r"(r[1]) : "r"(a));
}
__device__ __forceinline__ void mma_bf16(float* c, const uint32_t* a, const uint32_t* b) {
    asm volatile(
        "mma.sync.aligned.m16n8k16.row.col.f32.bf16.bf16.f32 "
        "{%0,%1,%2,%3}, {%4,%5,%6,%7}, {%8,%9}, {%0,%1,%2,%3};"
        : "+f"(c[0]), "+f"(c[1]), "+f"(c[2]), "+f"(c[3])
        : "r"(a[0]), "r"(a[1]), "r"(a[2]), "r"(a[3]), "r"(b[0]), "r"(b[1]));
}
// ---- cp.async ----
__device__ __forceinline__ void cpa16(uint32_t dst, const void* src) {
    asm volatile("cp.async.cg.shared.global [%0], [%1], 16;" :: "r"(dst), "l"(src));
}
__device__ __forceinline__ void cpa_commit() { asm volatile("cp.async.commit_group;"); }
template<int N> __device__ __forceinline__ void cpa_wait() {
    asm volatile("cp.async.wait_group %0;" :: "n"(N));
}
// nrows x 256B swizzled tile via cp.async (256 threads)
__device__ __forceinline__ void cp_tile256(uint32_t dst, const uint4* __restrict__ src,
                                           int nrows, int rs_u4, int tid) {
    int n = nrows * 16;
    for (int idx = tid; idx < n; idx += 256) {
        int r = idx >> 4, c8 = idx & 15;
        cpa16(dst + sw16(r, c8), src + r * rs_u4 + c8);
    }
}
// 128 rows x 128B swizzled tile via cp.async
__device__ __forceinline__ void cp_tile128(uint32_t dst, const uint4* __restrict__ src,
                                           int rs_u4, int tid) {
#pragma unroll
    for (int i = 0; i < 4; ++i) {
        int idx = tid + i * 256;
        int r = idx >> 3, c8 = idx & 7;
        cpa16(dst + sw16_64(r, c8), src + r * rs_u4 + c8);
    }
}

// C[128][128] += A(128x128k) @ Bt(128n x 128k)^T, bf16 3-split (256B-row tiles)
__device__ __forceinline__ void mma_nt(float (&acc)[4][4][4],
                                       uint32_t aHi, uint32_t aLo,
                                       uint32_t bHi, uint32_t bLo,
                                       int warp_m, int warp_n, int lane) {
#pragma unroll
    for (int k8 = 0; k8 < 8; ++k8) {
        uint32_t aH[4][4], aL[4][4], bH[4][2], bL[4][2];
        int ar = warp_m * 64 + (lane & 15);
        int ac8 = k8 * 2 + (lane >> 4);
#pragma unroll
        for (int mi = 0; mi < 4; ++mi) {
            uint32_t off = sw16(ar + mi * 16, ac8);
            ldsm4(aH[mi], aHi + off);
            ldsm4(aL[mi], aLo + off);
        }
        int l15 = lane & 15;
        int br = warp_n * 32 + (l15 & 7);
        int bc8 = k8 * 2 + (l15 >> 3);
#pragma unroll
        for (int ni = 0; ni < 4; ++ni) {
            uint32_t off = sw16(br + ni * 8, bc8);
            ldsm2(bH[ni], bHi + off);
            ldsm2(bL[ni], bLo + off);
        }
#pragma unroll
        for (int mi = 0; mi < 4; ++mi)
#pragma unroll
            for (int ni = 0; ni < 4; ++ni) {
                mma_bf16(acc[mi][ni], aH[mi], bH[ni]);
                mma_bf16(acc[mi][ni], aH[mi], bL[ni]);
                mma_bf16(acc[mi][ni], aL[mi], bH[ni]);
            }
    }
}

// u[128][64] = A(128x128k) @ Bt(64n x 128k)^T  (B tile 64 rows, 256B rows)
__device__ __forceinline__ void mma_n64(float (&u)[4][2][4],
                                        uint32_t aHi, uint32_t aLo,
                                        uint32_t bHi, uint32_t bLo,
                                        int warp_m, int warp_n, int lane) {
#pragma unroll
    for (int k8 = 0; k8 < 8; ++k8) {
        uint32_t aH[4][4], aL[4][4], bH[2][2], bL[2][2];
        int ar = warp_m * 64 + (lane & 15);
        int ac8 = k8 * 2 + (lane >> 4);
#pragma unroll
        for (int mi = 0; mi < 4; ++mi) {
            uint32_t off = sw16(ar + mi * 16, ac8);
            ldsm4(aH[mi], aHi + off);
            ldsm4(aL[mi], aLo + off);
        }
        int l15 = lane & 15;
        int br = warp_n * 16 + (l15 & 7);
        int bc8 = k8 * 2 + (l15 >> 3);
#pragma unroll
        for (int ni = 0; ni < 2; ++ni) {
            uint32_t off = sw16(br + ni * 8, bc8);
            ldsm2(bH[ni], bHi + off);
            ldsm2(bL[ni], bLo + off);
        }
#pragma unroll
        for (int mi = 0; mi < 4; ++mi)
#pragma unroll
            for (int ni = 0; ni < 2; ++ni) {
                mma_bf16(u[mi][ni], aH[mi], bH[ni]);
                mma_bf16(u[mi][ni], aH[mi], bL[ni]);
                mma_bf16(u[mi][ni], aL[mi], bH[ni]);
            }
    }
}

// C[128][128] += F(128m x 64k) @ Bt(128n x 64k)^T  (128B-row tiles)
__device__ __forceinline__ void mma_k64(float (&acc)[4][4][4],
                                        uint32_t fHi, uint32_t fLo,
                                        uint32_t bHi, uint32_t bLo,
                                        int warp_m, int warp_n, int lane) {
#pragma unroll
    for (int k8 = 0; k8 < 4; ++k8) {
        uint32_t aH[4][4], aL[4][4], bH[4][2], bL[4][2];
        int ar = warp_m * 64 + (lane & 15);
        int ac8 = k8 * 2 + (lane >> 4);
#pragma unroll
        for (int mi = 0; mi < 4; ++mi) {
            uint32_t off = sw16_64(ar + mi * 16, ac8);
            ldsm4(aH[mi], fHi + off);
            ldsm4(aL[mi], fLo + off);
        }
        int l15 = lane & 15;
        int br = warp_n * 32 + (l15 & 7);
        int bc8 = k8 * 2 + (l15 >> 3);
#pragma unroll
        for (int ni = 0; ni < 4; ++ni) {
            uint32_t off = sw16_64(br + ni * 8, bc8);
            ldsm2(bH[ni], bHi + off);
            ldsm2(bL[ni], bLo + off);
        }
#pragma unroll
        for (int mi = 0; mi < 4; ++mi)
#pragma unroll
            for (int ni = 0; ni < 4; ++ni) {
                mma_bf16(acc[mi][ni], aH[mi], bH[ni]);
                mma_bf16(acc[mi][ni], aH[mi], bL[ni]);
                mma_bf16(acc[mi][ni], aL[mi], bH[ni]);
            }
    }
}

// Gram: C += H^T @ H, bf16 3-split; trans loads of row-major H tile.
__device__ __forceinline__ void mma_tt(float (&acc)[4][4][4],
                                       uint32_t hHi, uint32_t hLo,
                                       int warp_m, int warp_n, int lane) {
#pragma unroll
    for (int k8 = 0; k8 < 8; ++k8) {
        int k0 = k8 * 16;
        uint32_t aH[4][4], aL[4][4], bH[4][2], bL[4][2];
        int ar = k0 + (lane & 7) + ((lane >> 4) << 3);
        int asel = (lane >> 3) & 1;
#pragma unroll
        for (int mi = 0; mi < 4; ++mi) {
            int c8 = ((warp_m * 64 + mi * 16) >> 3) + asel;
            uint32_t off = sw16(ar, c8);
            ldsm4t(aH[mi], hHi + off);
            ldsm4t(aL[mi], hLo + off);
        }
        int l15 = lane & 15;
        int br = k0 + (l15 & 7) + ((l15 >> 3) << 3);
#pragma unroll
        for (int ni = 0; ni < 4; ++ni) {
            int c8 = (warp_n * 32 + ni * 8) >> 3;
            uint32_t off = sw16(br, c8);
            ldsm2t(bH[ni], hHi + off);
            ldsm2t(bL[ni], hLo + off);
        }
#pragma unroll
        for (int mi = 0; mi < 4; ++mi)
#pragma unroll
            for (int ni = 0; ni < 4; ++ni) {
                mma_bf16(acc[mi][ni], aH[mi], bH[ni]);
                mma_bf16(acc[mi][ni], aH[mi], bL[ni]);
                mma_bf16(acc[mi][ni], aL[mi], bH[ni]);
            }
    }
}

// LayerNorm of fragment-layout values -> split hi/lo into swizzled 256B-row tile.
template<bool ENDSYNC>
__device__ __forceinline__ void ln_acc(const float (&v)[4][4][4],
                                       const float* gs, const float* bs,
                                       char* Ahi, char* Alo,
                                       float2* red,
                                       int warp_m, int warp_n, int lane, int tid) {
    int row0 = warp_m * 64 + (lane >> 2);
    int col0 = warp_n * 32 + (lane & 3) * 2;
#pragma unroll
    for (int mi = 0; mi < 4; ++mi) {
        float s1 = 0, q1 = 0, s2 = 0, q2 = 0;
#pragma unroll
        for (int ni = 0; ni < 4; ++ni) {
            s1 += v[mi][ni][0] + v[mi][ni][1];
            q1 += v[mi][ni][0] * v[mi][ni][0] + v[mi][ni][1] * v[mi][ni][1];
            s2 += v[mi][ni][2] + v[mi][ni][3];
            q2 += v[mi][ni][2] * v[mi][ni][2] + v[mi][ni][3] * v[mi][ni][3];
        }
        s1 += __shfl_xor_sync(~0u, s1, 1); s1 += __shfl_xor_sync(~0u, s1, 2);
        q1 += __shfl_xor_sync(~0u, q1, 1); q1 += __shfl_xor_sync(~0u, q1, 2);
        s2 += __shfl_xor_sync(~0u, s2, 1); s2 += __shfl_xor_sync(~0u, s2, 2);
        q2 += __shfl_xor_sync(~0u, q2, 1); q2 += __shfl_xor_sync(~0u, q2, 2);
        if ((lane & 3) == 0) {
            int r1 = row0 + mi * 16;
            red[r1 * 4 + warp_n] = make_float2(s1, q1);
            red[(r1 + 8) * 4 + warp_n] = make_float2(s2, q2);
        }
    }
    __syncthreads();
#pragma unroll
    for (int mi = 0; mi < 4; ++mi) {
        int r1 = row0 + mi * 16;
        float s1 = 0, q1 = 0, s2 = 0, q2 = 0;
#pragma unroll
        for (int w = 0; w < 4; ++w) {
            float2 p1 = red[r1 * 4 + w];
            float2 p2 = red[(r1 + 8) * 4 + w];
            s1 += p1.x; q1 += p1.y;
            s2 += p2.x; q2 += p2.y;
        }
        float m1 = s1 * (1.0f / 128.0f);
        float rs1 = rsqrtf(q1 * (1.0f / 128.0f) - m1 * m1 + EPSm);
        float m2 = s2 * (1.0f / 128.0f);
        float rs2 = rsqrtf(q2 * (1.0f / 128.0f) - m2 * m2 + EPSm);
#pragma unroll
        for (int ni = 0; ni < 4; ++ni) {
            int col = col0 + ni * 8;
            float g0 = gs[col], g1 = gs[col + 1], bb0 = bs[col], bb1 = bs[col + 1];
            int r2 = r1 + 8;
            float f0 = (v[mi][ni][0] - m1) * rs1 * g0 + bb0;
            float f1 = (v[mi][ni][1] - m1) * rs1 * g1 + bb1;
            float f2 = (v[mi][ni][2] - m2) * rs2 * g0 + bb0;
            float f3 = (v[mi][ni][3] - m2) * rs2 * g1 + bb1;
            uint32_t h, l;
            uint32_t o1 = sw4(r1, col), o2 = sw4(r2, col);
            split2(f0, f1, h, l);
            *reinterpret_cast<uint32_t*>(Ahi + o1) = h;
            *reinterpret_cast<uint32_t*>(Alo + o1) = l;
            split2(f2, f3, h, l);
            *reinterpret_cast<uint32_t*>(Ahi + o2) = h;
            *reinterpret_cast<uint32_t*>(Alo + o2) = l;
        }
    }
    if (ENDSYNC) __syncthreads();
}

// ============================ kernels ============================

// Unified prologue kernel:
//   blocks [0, 1024): t=0 gram partials (h = LN1(x); part = h^T h)
//   blocks [1024, 1056): QK = Qw @ Kw^T
//   blocks [1056, 1632): bf16 hi/lo weight splits
#define PREP_SMEM 71680
__global__ void __launch_bounds__(256, 1)
kprep_all(const float* __restrict__ xin,
          const float* __restrict__ lng, const float* __restrict__ lnb,
          const float* __restrict__ Qw, const float* __restrict__ Kw,
          const float* __restrict__ w1, const float* __restrict__ w2,
          const float* __restrict__ outw) {
    extern __shared__ char sm[];
    int b = blockIdx.x;
    int tid = threadIdx.x;

    if (b < 1024) {
        // ---- gram0 tile ----
        float* gs = reinterpret_cast<float*>(sm);
        float* bs = gs + 128;
        float2* red = reinterpret_cast<float2*>(sm + 1024);
        char* Hhi = sm + 6144;
        char* Hlo = sm + 6144 + 32768;
        uint32_t smb = smem_u32(sm);
        int lane = tid & 31, wid = tid >> 5;
        int warp_m = wid & 1, warp_n = wid >> 1;
        int row0 = warp_m * 64 + (lane >> 2);
        int col0 = warp_n * 32 + (lane & 3) * 2;
        if (tid < 128) { gs[tid] = lng[tid]; bs[tid] = lnb[tid]; }
        __syncthreads();

        const float* xt = xin + (size_t)b * 16384;
        float v[4][4][4];
#pragma unroll
        for (int mi = 0; mi < 4; ++mi)
#pragma unroll
            for (int ni = 0; ni < 4; ++ni) {
                const float* p = xt + (row0 + mi * 16) * 128 + col0 + ni * 8;
                float2 a = *reinterpret_cast<const float2*>(p);
                float2 bb = *reinterpret_cast<const float2*>(p + 8 * 128);
                v[mi][ni][0] = a.x; v[mi][ni][1] = a.y;
                v[mi][ni][2] = bb.x; v[mi][ni][3] = bb.y;
            }
        ln_acc<true>(v, gs, bs, Hhi, Hlo, red, warp_m, warp_n, lane, tid);

        float acc[4][4][4];
#pragma unroll
        for (int mi = 0; mi < 4; ++mi)
#pragma unroll
            for (int ni = 0; ni < 4; ++ni)
#pragma unroll
                for (int e = 0; e < 4; ++e) acc[mi][ni][e] = 0.f;
        mma_tt(acc, smb + 6144, smb + 6144 + 32768, warp_m, warp_n, lane);

        float* dst = g_part + (size_t)b * 16384;
#pragma unroll
        for (int mi = 0; mi < 4; ++mi)
#pragma unroll
            for (int ni = 0; ni < 4; ++ni) {
                int r1 = row0 + mi * 16, col = col0 + ni * 8;
                __stcs(reinterpret_cast<float2*>(dst + r1 * 128 + col),
                       make_float2(acc[mi][ni][0], acc[mi][ni][1]));
                __stcs(reinterpret_cast<float2*>(dst + (r1 + 8) * 128 + col),
                       make_float2(acc[mi][ni][2], acc[mi][ni][3]));
            }
    } else if (b < 1056) {
        // ---- QK = Qw @ Kw^T ----
        float* Bs = reinterpret_cast<float*>(sm);          // [128][129]
        float* As = Bs + 128 * 129;                        // [4][128]
        for (int idx = tid; idx < 16384; idx += 256)
            Bs[(idx >> 7) * 129 + (idx & 127)] = Kw[idx];
        int r0 = (b - 1024) * 4;
        for (int idx = tid; idx < 512; idx += 256)
            As[idx] = Qw[(r0 + (idx >> 7)) * 128 + (idx & 127)];
        __syncthreads();
        int j = tid & 127, i0 = (tid >> 7) * 2;
        float c0 = 0.f, c1 = 0.f;
#pragma unroll 8
        for (int k = 0; k < 128; ++k) {
            float bb = Bs[j * 129 + k];
            c0 = fmaf(As[i0 * 128 + k], bb, c0);
            c1 = fmaf(As[i0 * 128 + 128 + k], bb, c1);
        }
        g_QK[(r0 + i0) * 128 + j] = c0;
        g_QK[(r0 + i0 + 1) * 128 + j] = c1;
    } else {
        // ---- weight splits ----
        int idx = (b - 1056) * 256 + tid;
        if (idx < 65536) {                 // w1t [512 n][128 k]
            int n = idx >> 7, k = idx & 127;
            sp1(w1[k * 512 + n], &g_w1t_hi[idx], &g_w1t_lo[idx]);
        } else if (idx < 131072) {         // w2t [128 n][512 k]
            int j = idx - 65536;
            int n = j >> 9, k = j & 511;
            sp1(w2[k * 128 + n], &g_w2t_hi[j], &g_w2t_lo[j]);
        } else if (idx < 147456) {         // owt [128 n][128 k]
            int j = idx - 131072;
            int n = j >> 7, k = j & 127;
            sp1(outw[k * 128 + n], &g_owt_hi[j], &g_owt_lo[j]);
        }
    }
}

// stage-1 reduce: 1024 partials -> 8 partials. 131072 threads, 128 loads each.
__global__ void kred1_kernel() {
    int idx = blockIdx.x * 256 + threadIdx.x;   // 0 .. 131071
    int e = idx & 16383;
    int g = idx >> 14;                           // 0..7
    const float* p = g_part + (size_t)g * 128 * 16384 + e;
    float s0 = 0.f, s1 = 0.f, s2 = 0.f, s3 = 0.f;
#pragma unroll 8
    for (int i = 0; i < 128; i += 4) {
        s0 += __ldcs(p + (size_t)(i + 0) * 16384);
        s1 += __ldcs(p + (size_t)(i + 1) * 16384);
        s2 += __ldcs(p + (size_t)(i + 2) * 16384);
        s3 += __ldcs(p + (size_t)(i + 3) * 16384);
    }
    g_part2[(size_t)g * 16384 + e] = (s0 + s1) + (s2 + s3);
}

// fused per-step mid kernel: phase1 T1 = G@Vw (G = sum of 8 g_part2 slabs),
// global barrier (32 resident CTAs), phase2 Mt = split(QK @ T1).
#define TS_SMEM (128 * 129 * 4 + 512 * 4)
__global__ void __launch_bounds__(256, 1)
kmid_kernel(const float* __restrict__ Vw) {
    extern __shared__ float ts[];
    float* Bs = ts;
    float* As = ts + 128 * 129;
    int tid = threadIdx.x;
    int r0 = blockIdx.x * 4;
    int j = tid & 127, i0 = (tid >> 7) * 2;

    // ---- phase 1: T1 = G @ Vw ----
    for (int idx = tid; idx < 16384; idx += 256)
        Bs[(idx >> 7) * 129 + (idx & 127)] = Vw[idx];
    for (int idx = tid; idx < 512; idx += 256) {
        int off = (r0 + (idx >> 7)) * 128 + (idx & 127);
        const float* p = g_part2 + off;
        float s = 0.f;
#pragma unroll
        for (int g = 0; g < 8; ++g) s += p[(size_t)g * 16384];
        As[idx] = s;
    }
    __syncthreads();
    {
        float c0 = 0.f, c1 = 0.f;
#pragma unroll 8
        for (int k = 0; k < 128; ++k) {
            float b = Bs[k * 129 + j];
            c0 = fmaf(As[i0 * 128 + k], b, c0);
            c1 = fmaf(As[i0 * 128 + 128 + k], b, c1);
        }
        g_T1[(r0 + i0) * 128 + j] = c0;
        g_T1[(r0 + i0 + 1) * 128 + j] = c1;
    }
    // ---- global barrier (all 32 CTAs resident; monotonic ticket) ----
    __threadfence();
    __syncthreads();
    if (tid == 0) {
        unsigned arrive = atomicAdd(&g_barrier, 1u);
        unsigned target = (arrive / 32u + 1u) * 32u;
        while (*reinterpret_cast<volatile unsigned*>(&g_barrier) < target)
            __nanosleep(64);
        __threadfence();
    }
    __syncthreads();
    // ---- phase 2: Mt = split(QK @ T1) ----
    for (int idx = tid; idx < 16384; idx += 256)
        Bs[(idx >> 7) * 129 + (idx & 127)] = __ldcg(g_T1 + idx);
    for (int idx = tid; idx < 512; idx += 256)
        As[idx] = g_QK[(r0 + (idx >> 7)) * 128 + (idx & 127)];
    __syncthreads();
    {
        float c0 = 0.f, c1 = 0.f;
#pragma unroll 8
        for (int k = 0; k < 128; ++k) {
            float b = Bs[k * 129 + j];
            c0 = fmaf(As[i0 * 128 + k], b, c0);
            c1 = fmaf(As[i0 * 128 + 128 + k], b, c1);
        }
        sp1(c0, &g_Mt_hi[j * 128 + r0 + i0], &g_Mt_lo[j * 128 + r0 + i0]);
        sp1(c1, &g_Mt_hi[j * 128 + r0 + i0 + 1], &g_Mt_lo[j * 128 + r0 + i0 + 1]);
    }
}

// ================= big fused kernel (HMMA + cp.async, 2-sync FF pipeline) =================
#define KC_RED  5120
#define KC_A    10240                  // Ahi 32K | Alo 32K
#define KC_B0   (KC_A + 65536)         // 32K (hi at +0, lo at +16384 for FF tiles)
#define KC_B1   (KC_B0 + 32768)
#define KC_F    (KC_B1 + 32768)        // Fhi 16K | Flo 16K
#define KC_SMEM (KC_F + 32768)         // 174080

__global__ void __launch_bounds__(256, 1)
kc_mma(const float* __restrict__ xin, int srcIsG,
       const float* __restrict__ ln1g, const float* __restrict__ ln1b,
       const float* __restrict__ ln2g, const float* __restrict__ ln2b,
       const float* __restrict__ b1, const float* __restrict__ b2,
       const float* __restrict__ outb, float* __restrict__ outp, int last) {
    extern __shared__ char sm[];
    uint32_t smb = smem_u32(sm);
    int tid = threadIdx.x, lane = tid & 31, wid = tid >> 5;
    int warp_m = wid & 1, warp_n = wid >> 1;
    int row0 = warp_m * 64 + (lane >> 2);
    int col0 = warp_n * 32 + (lane & 3) * 2;

    float* ln1gs = reinterpret_cast<float*>(sm);
    float* ln1bs = ln1gs + 128;
    float* ln2gs = ln1gs + 256;
    float* ln2bs = ln1gs + 384;
    float* b2s   = ln1gs + 512;
    float* outbs = ln1gs + 640;
    float* b1s   = ln1gs + 768;     // 512 floats
    float2* red  = reinterpret_cast<float2*>(sm + KC_RED);
    if (tid < 128) {
        ln1gs[tid] = ln1g[tid]; ln1bs[tid] = ln1b[tid];
        ln2gs[tid] = ln2g[tid]; ln2bs[tid] = ln2b[tid];
        b2s[tid] = b2[tid]; outbs[tid] = outb[tid];
    }
    b1s[tid] = b1[tid]; b1s[tid + 256] = b1[tid + 256];

    // prefetch Mt (hi -> B0, lo -> B1), overlapped with x load + LN1
    cp_tile256(smb + KC_B0, reinterpret_cast<const uint4*>(g_Mt_hi), 128, 16, tid);
    cp_tile256(smb + KC_B1, reinterpret_cast<const uint4*>(g_Mt_lo), 128, 16, tid);
    cpa_commit();

    // x in fragment layout
    size_t base = (size_t)blockIdx.x * 16384;
    const float* xt = (srcIsG ? g_x : xin) + base;
    float xr[4][4][4];
#pragma unroll
    for (int mi = 0; mi < 4; ++mi)
#pragma unroll
        for (int ni = 0; ni < 4; ++ni) {
            const float* p = xt + (row0 + mi * 16) * 128 + col0 + ni * 8;
            float2 a = *reinterpret_cast<const float2*>(p);
            float2 b = *reinterpret_cast<const float2*>(p + 8 * 128);
            xr[mi][ni][0] = a.x; xr[mi][ni][1] = a.y;
            xr[mi][ni][2] = b.x; xr[mi][ni][3] = b.y;
        }

    // A <- LN1(x)  (end-sync folded into the cpa_wait sync below)
    ln_acc<false>(xr, ln1gs, ln1bs, sm + KC_A, sm + KC_A + 32768, red, warp_m, warp_n, lane, tid);
    cpa_wait<0>();
    __syncthreads();
    // x += h @ M
    mma_nt(xr, smb + KC_A, smb + KC_A + 32768, smb + KC_B0, smb + KC_B1, warp_m, warp_n, lane);
    __syncthreads();

    // prime FF pipeline: w1 sub-chunk 0 -> B0
    cp_tile256(smb + KC_B0,         reinterpret_cast<const uint4*>(g_w1t_hi), 64, 16, tid);
    cp_tile256(smb + KC_B0 + 16384, reinterpret_cast<const uint4*>(g_w1t_lo), 64, 16, tid);
    cpa_commit();

    // A <- LN2(x)  (end-sync folded into the cpa_wait sync below)
    ln_acc<false>(xr, ln2gs, ln2bs, sm + KC_A, sm + KC_A + 32768, red, warp_m, warp_n, lane, tid);
    cpa_wait<0>();       // w1_0 landed
    __syncthreads();     // w1_0 + A visible

    // FF: 8 sub-chunks of 64 hidden units, double-buffered weights, 2 syncs/iter
#pragma unroll 1
    for (int c = 0; c < 8; ++c) {
        // prefetch w2_c -> B1 (overlaps mma1 + relu)
        cp_tile128(smb + KC_B1,         reinterpret_cast<const uint4*>(g_w2t_hi) + c * 8, 64, tid);
        cp_tile128(smb + KC_B1 + 16384, reinterpret_cast<const uint4*>(g_w2t_lo) + c * 8, 64, tid);
        cpa_commit();
        float u[4][2][4];
#pragma unroll
        for (int mi = 0; mi < 4; ++mi)
#pragma unroll
            for (int ni = 0; ni < 2; ++ni)
#pragma unroll
                for (int e = 0; e < 4; ++e) u[mi][ni][e] = 0.f;
        mma_n64(u, smb + KC_A, smb + KC_A + 32768, smb + KC_B0, smb + KC_B0 + 16384,
                warp_m, warp_n, lane);
        // bias + relu + split -> F
#pragma unroll
        for (int mi = 0; mi < 4; ++mi)
#pragma unroll
            for (int ni = 0; ni < 2; ++ni) {
                int hcol = warp_n * 16 + (lane & 3) * 2 + ni * 8;      // 0..63
                float bb0 = b1s[c * 64 + hcol], bb1 = b1s[c * 64 + hcol + 1];
                int r1 = row0 + mi * 16, r2 = r1 + 8;
                float f0 = fmaxf(u[mi][ni][0] + bb0, 0.f);
                float f1 = fmaxf(u[mi][ni][1] + bb1, 0.f);
                float f2 = fmaxf(u[mi][ni][2] + bb0, 0.f);
                float f3 = fmaxf(u[mi][ni][3] + bb1, 0.f);
                uint32_t h, l;
                uint32_t o1 = sw4_64(r1, hcol), o2 = sw4_64(r2, hcol);
                split2(f0, f1, h, l);
                *reinterpret_cast<uint32_t*>(sm + KC_F + o1) = h;
                *reinterpret_cast<uint32_t*>(sm + KC_F + 16384 + o1) = l;
                split2(f2, f3, h, l);
                *reinterpret_cast<uint32_t*>(sm + KC_F + o2) = h;
                *reinterpret_cast<uint32_t*>(sm + KC_F + 16384 + o2) = l;
            }
        cpa_wait<0>();       // w2_c landed
        __syncthreads();     // F + w2_c visible; B0 (w1_c) free
        // prefetch w1_{c+1} -> B0 (overlaps mma2); last iter: owt_hi if needed
        if (c < 7) {
            cp_tile256(smb + KC_B0,         reinterpret_cast<const uint4*>(g_w1t_hi) + (c + 1) * 1024, 64, 16, tid);
            cp_tile256(smb + KC_B0 + 16384, reinterpret_cast<const uint4*>(g_w1t_lo) + (c + 1) * 1024, 64, 16, tid);
        } else if (last) {
            cp_tile256(smb + KC_B0, reinterpret_cast<const uint4*>(g_owt_hi), 128, 16, tid);
        }
        cpa_commit();
        mma_k64(xr, smb + KC_F, smb + KC_F + 16384, smb + KC_B1, smb + KC_B1 + 16384,
                warp_m, warp_n, lane);
        cpa_wait<0>();       // w1_{c+1} (or owt_hi) landed
        __syncthreads();     // B1/F free; next tile visible
    }

    // + b2
#pragma unroll
    for (int mi = 0; mi < 4; ++mi)
#pragma unroll
        for (int ni = 0; ni < 4; ++ni) {
            int col = col0 + ni * 8;
            xr[mi][ni][0] += b2s[col];     xr[mi][ni][1] += b2s[col + 1];
            xr[mi][ni][2] += b2s[col];     xr[mi][ni][3] += b2s[col + 1];
        }

    if (!last) {
        // store x_new
        float* dst = g_x + base;
#pragma unroll
        for (int mi = 0; mi < 4; ++mi)
#pragma unroll
            for (int ni = 0; ni < 4; ++ni) {
                int r1 = row0 + mi * 16, col = col0 + ni * 8;
                *reinterpret_cast<float2*>(dst + r1 * 128 + col) =
                    make_float2(xr[mi][ni][0], xr[mi][ni][1]);
                *reinterpret_cast<float2*>(dst + (r1 + 8) * 128 + col) =
                    make_float2(xr[mi][ni][2], xr[mi][ni][3]);
            }
        // fused Gram partial for the NEXT step: h = LN1(x_new); part = h^T h
        ln_acc<true>(xr, ln1gs, ln1bs, sm + KC_A, sm + KC_A + 32768, red, warp_m, warp_n, lane, tid);
        float ga[4][4][4];
#pragma unroll
        for (int mi = 0; mi < 4; ++mi)
#pragma unroll
            for (int ni = 0; ni < 4; ++ni)
#pragma unroll
                for (int e = 0; e < 4; ++e) ga[mi][ni][e] = 0.f;
        mma_tt(ga, smb + KC_A, smb + KC_A + 32768, warp_m, warp_n, lane);
        float* pdst = g_part + (size_t)blockIdx.x * 16384;
#pragma unroll
        for (int mi = 0; mi < 4; ++mi)
#pragma unroll
            for (int ni = 0; ni < 4; ++ni) {
                int r1 = row0 + mi * 16, col = col0 + ni * 8;
                __stcs(reinterpret_cast<float2*>(pdst + r1 * 128 + col),
                       make_float2(ga[mi][ni][0], ga[mi][ni][1]));
                __stcs(reinterpret_cast<float2*>(pdst + (r1 + 8) * 128 + col),
                       make_float2(ga[mi][ni][2], ga[mi][ni][3]));
            }
    } else {
        // out = x @ outw + outb  (owt_hi already landed in B0 at loop end)
        cp_tile256(smb + KC_B1, reinterpret_cast<const uint4*>(g_owt_lo), 128, 16, tid);
        cpa_commit();
        // split x -> A
#pragma unroll
        for (int mi = 0; mi < 4; ++mi)
#pragma unroll
            for (int ni = 0; ni < 4; ++ni) {
                int col = col0 + ni * 8;
                int r1 = row0 + mi * 16, r2 = r1 + 8;
                uint32_t h, l;
                uint32_t o1 = sw4(r1, col), o2 = sw4(r2, col);
                split2(xr[mi][ni][0], xr[mi][ni][1], h, l);
                *reinterpret_cast<uint32_t*>(sm + KC_A + o1) = h;
                *reinterpret_cast<uint32_t*>(sm + KC_A + 32768 + o1) = l;
                split2(xr[mi][ni][2], xr[mi][ni][3], h, l);
                *reinterpret_cast<uint32_t*>(sm + KC_A + o2) = h;
                *reinterpret_cast<uint32_t*>(sm + KC_A + 32768 + o2) = l;
            }
        cpa_wait<0>();
        __syncthreads();
        float o[4][4][4];
#pragma unroll
        for (int mi = 0; mi < 4; ++mi)
#pragma unroll
            for (int ni = 0; ni < 4; ++ni)
#pragma unroll
                for (int e = 0; e < 4; ++e) o[mi][ni][e] = 0.f;
        mma_nt(o, smb + KC_A, smb + KC_A + 32768, smb + KC_B0, smb + KC_B1, warp_m, warp_n, lane);
        float* dst = outp + base;
#pragma unroll
        for (int mi = 0; mi < 4; ++mi)
#pragma unroll
            for (int ni = 0; ni < 4; ++ni) {
                int r1 = row0 + mi * 16, col = col0 + ni * 8;
                *reinterpret_cast<float2*>(dst + r1 * 128 + col) =
                    make_float2(o[mi][ni][0] + outbs[col], o[mi][ni][1] + outbs[col + 1]);
                *reinterpret_cast<float2*>(dst + (r1 + 8) * 128 + col) =
                    make_float2(o[mi][ni][2] + outbs[col], o[mi][ni][3] + outbs[col + 1]);
            }
    }
}

// ============================ host launcher ============================
extern "C" void kernel_launch(void* const* d_in, const int* in_sizes, int n_in,
                              void* d_out, int out_size) {
    (void)in_sizes; (void)n_in; (void)out_size;
    const float* x    = (const float*)d_in[0];
    const float* Kw   = (const float*)d_in[1];
    const float* Qw   = (const float*)d_in[2];
    const float* Vw   = (const float*)d_in[3];
    const float* ln1g = (const float*)d_in[4];
    const float* ln1b = (const float*)d_in[5];
    const float* ln2g = (const float*)d_in[6];
    const float* ln2b = (const float*)d_in[7];
    const float* w1   = (const float*)d_in[8];
    const float* b1   = (const float*)d_in[9];
    const float* w2   = (const float*)d_in[10];
    const float* b2   = (const float*)d_in[11];
    const float* outw = (const float*)d_in[12];
    const float* outb = (const float*)d_in[13];
    float* out = (float*)d_out;

    cudaFuncSetAttribute(kc_mma, cudaFuncAttributeMaxDynamicSharedMemorySize, KC_SMEM);
    cudaFuncSetAttribute(kprep_all, cudaFuncAttributeMaxDynamicSharedMemorySize, PREP_SMEM);
    cudaFuncSetAttribute(kmid_kernel, cudaFuncAttributeMaxDynamicSharedMemorySize, TS_SMEM);

    // single prologue launch: gram0 + QK + weight splits
    kprep_all<<<1632, 256, PREP_SMEM>>>(x, ln1g, ln1b, Qw, Kw, w1, w2, outw);

    for (int t = 0; t < 4; ++t) {
        int srcIsG = (t != 0);
        kred1_kernel<<<512, 256>>>();                 // 1024 -> 8 partials
        kmid_kernel<<<32, 256, TS_SMEM>>>(Vw);        // T1 = G@Vw ; Mt = split(QK@T1)
        kc_mma<<<NTILESm, 256, KC_SMEM>>>(x, srcIsG, ln1g, ln1b, ln2g, ln2b,
                                          b1, b2, outb, out, t == 3);
    }
}

// round 16
// speedup vs baseline: 1.1957x; 1.1791x over previous
#include <cuda_runtime.h>
#include <cuda_bf16.h>
#include <cuda_fp16.h>
#include <cstdint>

#define EPSm   1e-5f
#define NROWSm 131072
#define NTILESm 1024
#define NPART  1024

// ---------------- device scratch ----------------
__device__ float g_x[NROWSm * 128];
__device__ float g_part[NPART * 128 * 128];   // 64 MB gram partials (stage 0)
__device__ float g_part2[8 * 128 * 128];      // 512 KB (stage 1)
__device__ float g_QK[128 * 128];
__device__ float g_T1[128 * 128];
__device__ unsigned g_barrier;                // monotonic ticket barrier for kmid
__device__ __nv_bfloat16 g_Mt_hi[128 * 128],  g_Mt_lo[128 * 128];   // attention (bf16 3-split)
__device__ __half g_w1h[512 * 128];           // FF weights, single fp16, [n][k]
__device__ __half g_w2h[128 * 512];           // [n][k]
__device__ __nv_bfloat16 g_owt_hi[128 * 128], g_owt_lo[128 * 128];  // out-proj (bf16 3-split)

// ---------------- helpers ----------------
__device__ __forceinline__ uint32_t smem_u32(const void* p) {
    uint32_t a;
    asm("{ .reg .u64 t; cvta.to.shared.u64 t, %1; cvt.u32.u64 %0, t; }" : "=r"(a) : "l"(p));
    return a;
}
// XOR-swizzled tile, 256B rows (128 x 2B cols)
__device__ __forceinline__ uint32_t sw16(int r, int c8) {
    return (uint32_t)(r * 256 + ((c8 ^ (r & 7)) << 4));
}
__device__ __forceinline__ uint32_t sw4(int r, int col) {
    return (uint32_t)(r * 256 + ((((col >> 3) ^ (r & 7)) << 4)) + (col & 7) * 2);
}
// XOR-swizzled tile, 128B rows (64 x 2B cols)
__device__ __forceinline__ uint32_t sw16_64(int r, int c8) {
    return (uint32_t)(r * 128 + ((((c8 ^ (r & 7)) & 7) << 4)));
}
__device__ __forceinline__ uint32_t sw4_64(int r, int col) {
    return (uint32_t)(r * 128 + ((((col >> 3) ^ (r & 7)) & 7) << 4) + (col & 7) * 2);
}
// bf16 hi/lo split (attention / gram / out-proj path)
__device__ __forceinline__ void split2(float f0, float f1, uint32_t& hi, uint32_t& lo) {
    __nv_bfloat162 H = __floats2bfloat162_rn(f0, f1);
    float r0 = f0 - __bfloat162float(H.x);
    float r1 = f1 - __bfloat162float(H.y);
    __nv_bfloat162 L = __floats2bfloat162_rn(r0, r1);
    hi = *reinterpret_cast<uint32_t*>(&H);
    lo = *reinterpret_cast<uint32_t*>(&L);
}
// fp16 hi/lo split (FF path)
__device__ __forceinline__ void split2h(float f0, float f1, uint32_t& hi, uint32_t& lo) {
    __half2 H = __floats2half2_rn(f0, f1);
    float r0 = f0 - __low2float(H);
    float r1 = f1 - __high2float(H);
    __half2 L = __floats2half2_rn(r0, r1);
    hi = *reinterpret_cast<uint32_t*>(&H);
    lo = *reinterpret_cast<uint32_t*>(&L);
}
__device__ __forceinline__ void sp1(float v, __nv_bfloat16* h, __nv_bfloat16* l) {
    __nv_bfloat16 hh = __float2bfloat16(v);
    *h = hh;
    *l = __float2bfloat16(v - __bfloat162float(hh));
}
__device__ __forceinline__ void ldsm4(uint32_t* r, uint32_t a) {
    asm volatile("ldmatrix.sync.aligned.m8n8.x4.shared.b16 {%0,%1,%2,%3}, [%4];"
                 : "=r"(r[0]), "=r"(r[1]), "=r"(r[2]), "=r"(r[3]) : "r"(a));
}
__device__ __forceinline__ void ldsm2(uint32_t* r, uint32_t a) {
    asm volatile("ldmatrix.sync.aligned.m8n8.x2.shared.b16 {%0,%1}, [%2];"
                 : "=r"(r[0]), "=r"(r[1]) : "r"(a));
}
__device__ __forceinline__ void ldsm4t(uint32_t* r, uint32_t a) {
    asm volatile("ldmatrix.sync.aligned.m8n8.x4.trans.shared.b16 {%0,%1,%2,%3}, [%4];"
                 : "=r"(r[0]), "=r"(r[1]), "=r"(r[2]), "=r"(r[3]) : "r"(a));
}
__device__ __forceinline__ void ldsm2t(uint32_t* r, uint32_t a) {
    asm volatile("ldmatrix.sync.aligned.m8n8.x2.trans.shared.b16 {%0,%1}, [%2];"
                 : "=r"(r[0]), "=r"(r[1]) : "r"(a));
}
__device__ __forceinline__ void mma_bf16(float* c, const uint32_t* a, const uint32_t* b) {
    asm volatile(
        "mma.sync.aligned.m16n8k16.row.col.f32.bf16.bf16.f32 "
        "{%0,%1,%2,%3}, {%4,%5,%6,%7}, {%8,%9}, {%0,%1,%2,%3};"
        : "+f"(c[0]), "+f"(c[1]), "+f"(c[2]), "+f"(c[3])
        : "r"(a[0]), "r"(a[1]), "r"(a[2]), "r"(a[3]), "r"(b[0]), "r"(b[1]));
}
__device__ __forceinline__ void mma_f16(float* c, const uint32_t* a, const uint32_t* b) {
    asm volatile(
        "mma.sync.aligned.m16n8k16.row.col.f32.f16.f16.f32 "
        "{%0,%1,%2,%3}, {%4,%5,%6,%7}, {%8,%9}, {%0,%1,%2,%3};"
        : "+f"(c[0]), "+f"(c[1]), "+f"(c[2]), "+f"(c[3])
        : "r"(a[0]), "r"(a[1]), "r"(a[2]), "r"(a[3]), "r"(b[0]), "r"(b[1]));
}
// ---- cp.async ----
__device__ __forceinline__ void cpa16(uint32_t dst, const void* src) {
    asm volatile("cp.async.cg.shared.global [%0], [%1], 16;" :: "r"(dst), "l"(src));
}
__device__ __forceinline__ void cpa_commit() { asm volatile("cp.async.commit_group;"); }
template<int N> __device__ __forceinline__ void cpa_wait() {
    asm volatile("cp.async.wait_group %0;" :: "n"(N));
}
// nrows x 256B swizzled tile via cp.async (256 threads)
__device__ __forceinline__ void cp_tile256(uint32_t dst, const uint4* __restrict__ src,
                                           int nrows, int rs_u4, int tid) {
    int n = nrows * 16;
    for (int idx = tid; idx < n; idx += 256) {
        int r = idx >> 4, c8 = idx & 15;
        cpa16(dst + sw16(r, c8), src + r * rs_u4 + c8);
    }
}
// 128 rows x 128B swizzled tile via cp.async
__device__ __forceinline__ void cp_tile128(uint32_t dst, const uint4* __restrict__ src,
                                           int rs_u4, int tid) {
#pragma unroll
    for (int i = 0; i < 4; ++i) {
        int idx = tid + i * 256;
        int r = idx >> 3, c8 = idx & 7;
        cpa16(dst + sw16_64(r, c8), src + r * rs_u4 + c8);
    }
}

// C[128][128] += A(128x128k) @ Bt(128n x 128k)^T, bf16 3-split (256B-row tiles)
__device__ __forceinline__ void mma_nt(float (&acc)[4][4][4],
                                       uint32_t aHi, uint32_t aLo,
                                       uint32_t bHi, uint32_t bLo,
                                       int warp_m, int warp_n, int lane) {
#pragma unroll
    for (int k8 = 0; k8 < 8; ++k8) {
        uint32_t aH[4][4], aL[4][4], bH[4][2], bL[4][2];
        int ar = warp_m * 64 + (lane & 15);
        int ac8 = k8 * 2 + (lane >> 4);
#pragma unroll
        for (int mi = 0; mi < 4; ++mi) {
            uint32_t off = sw16(ar + mi * 16, ac8);
            ldsm4(aH[mi], aHi + off);
            ldsm4(aL[mi], aLo + off);
        }
        int l15 = lane & 15;
        int br = warp_n * 32 + (l15 & 7);
        int bc8 = k8 * 2 + (l15 >> 3);
#pragma unroll
        for (int ni = 0; ni < 4; ++ni) {
            uint32_t off = sw16(br + ni * 8, bc8);
            ldsm2(bH[ni], bHi + off);
            ldsm2(bL[ni], bLo + off);
        }
#pragma unroll
        for (int mi = 0; mi < 4; ++mi)
#pragma unroll
            for (int ni = 0; ni < 4; ++ni) {
                mma_bf16(acc[mi][ni], aH[mi], bH[ni]);
                mma_bf16(acc[mi][ni], aH[mi], bL[ni]);
                mma_bf16(acc[mi][ni], aL[mi], bH[ni]);
            }
    }
}

// FF GEMM1: u[128][64] = A(fp16 hi/lo, 128x128k) @ w1(64n x 128k single fp16)^T
__device__ __forceinline__ void mma_n64h(float (&u)[4][2][4],
                                         uint32_t aHi, uint32_t aLo, uint32_t bS,
                                         int warp_m, int warp_n, int lane) {
#pragma unroll
    for (int k8 = 0; k8 < 8; ++k8) {
        uint32_t aH[4][4], aL[4][4], bF[2][2];
        int ar = warp_m * 64 + (lane & 15);
        int ac8 = k8 * 2 + (lane >> 4);
#pragma unroll
        for (int mi = 0; mi < 4; ++mi) {
            uint32_t off = sw16(ar + mi * 16, ac8);
            ldsm4(aH[mi], aHi + off);
            ldsm4(aL[mi], aLo + off);
        }
        int l15 = lane & 15;
        int br = warp_n * 16 + (l15 & 7);
        int bc8 = k8 * 2 + (l15 >> 3);
#pragma unroll
        for (int ni = 0; ni < 2; ++ni)
            ldsm2(bF[ni], bS + sw16(br + ni * 8, bc8));
#pragma unroll
        for (int mi = 0; mi < 4; ++mi)
#pragma unroll
            for (int ni = 0; ni < 2; ++ni) {
                mma_f16(u[mi][ni], aH[mi], bF[ni]);
                mma_f16(u[mi][ni], aL[mi], bF[ni]);
            }
    }
}

// FF GEMM2: C += F(fp16 hi/lo, 128m x 64k) @ w2(128n x 64k single fp16)^T
__device__ __forceinline__ void mma_k64h(float (&acc)[4][4][4],
                                         uint32_t fHi, uint32_t fLo, uint32_t bS,
                                         int warp_m, int warp_n, int lane) {
#pragma unroll
    for (int k8 = 0; k8 < 4; ++k8) {
        uint32_t aH[4][4], aL[4][4], bF[4][2];
        int ar = warp_m * 64 + (lane & 15);
        int ac8 = k8 * 2 + (lane >> 4);
#pragma unroll
        for (int mi = 0; mi < 4; ++mi) {
            uint32_t off = sw16_64(ar + mi * 16, ac8);
            ldsm4(aH[mi], fHi + off);
            ldsm4(aL[mi], fLo + off);
        }
        int l15 = lane & 15;
        int br = warp_n * 32 + (l15 & 7);
        int bc8 = k8 * 2 + (l15 >> 3);
#pragma unroll
        for (int ni = 0; ni < 4; ++ni)
            ldsm2(bF[ni], bS + sw16_64(br + ni * 8, bc8));
#pragma unroll
        for (int mi = 0; mi < 4; ++mi)
#pragma unroll
            for (int ni = 0; ni < 4; ++ni) {
                mma_f16(acc[mi][ni], aH[mi], bF[ni]);
                mma_f16(acc[mi][ni], aL[mi], bF[ni]);
            }
    }
}

// Gram: C += H^T @ H, bf16 3-split; trans loads of row-major H tile.
__device__ __forceinline__ void mma_tt(float (&acc)[4][4][4],
                                       uint32_t hHi, uint32_t hLo,
                                       int warp_m, int warp_n, int lane) {
#pragma unroll
    for (int k8 = 0; k8 < 8; ++k8) {
        int k0 = k8 * 16;
        uint32_t aH[4][4], aL[4][4], bH[4][2], bL[4][2];
        int ar = k0 + (lane & 7) + ((lane >> 4) << 3);
        int asel = (lane >> 3) & 1;
#pragma unroll
        for (int mi = 0; mi < 4; ++mi) {
            int c8 = ((warp_m * 64 + mi * 16) >> 3) + asel;
            uint32_t off = sw16(ar, c8);
            ldsm4t(aH[mi], hHi + off);
            ldsm4t(aL[mi], hLo + off);
        }
        int l15 = lane & 15;
        int br = k0 + (l15 & 7) + ((l15 >> 3) << 3);
#pragma unroll
        for (int ni = 0; ni < 4; ++ni) {
            int c8 = (warp_n * 32 + ni * 8) >> 3;
            uint32_t off = sw16(br, c8);
            ldsm2t(bH[ni], hHi + off);
            ldsm2t(bL[ni], hLo + off);
        }
#pragma unroll
        for (int mi = 0; mi < 4; ++mi)
#pragma unroll
            for (int ni = 0; ni < 4; ++ni) {
                mma_bf16(acc[mi][ni], aH[mi], bH[ni]);
                mma_bf16(acc[mi][ni], aH[mi], bL[ni]);
                mma_bf16(acc[mi][ni], aL[mi], bH[ni]);
            }
    }
}

// LayerNorm of fragment-layout values -> split hi/lo into swizzled 256B-row tile.
// FP16 selects fp16 split (FF path) vs bf16 split (attention/gram path).
template<bool ENDSYNC, bool FP16>
__device__ __forceinline__ void ln_acc(const float (&v)[4][4][4],
                                       const float* gs, const float* bs,
                                       char* Ahi, char* Alo,
                                       float2* red,
                                       int warp_m, int warp_n, int lane, int tid) {
    int row0 = warp_m * 64 + (lane >> 2);
    int col0 = warp_n * 32 + (lane & 3) * 2;
#pragma unroll
    for (int mi = 0; mi < 4; ++mi) {
        float s1 = 0, q1 = 0, s2 = 0, q2 = 0;
#pragma unroll
        for (int ni = 0; ni < 4; ++ni) {
            s1 += v[mi][ni][0] + v[mi][ni][1];
            q1 += v[mi][ni][0] * v[mi][ni][0] + v[mi][ni][1] * v[mi][ni][1];
            s2 += v[mi][ni][2] + v[mi][ni][3];
            q2 += v[mi][ni][2] * v[mi][ni][2] + v[mi][ni][3] * v[mi][ni][3];
        }
        s1 += __shfl_xor_sync(~0u, s1, 1); s1 += __shfl_xor_sync(~0u, s1, 2);
        q1 += __shfl_xor_sync(~0u, q1, 1); q1 += __shfl_xor_sync(~0u, q1, 2);
        s2 += __shfl_xor_sync(~0u, s2, 1); s2 += __shfl_xor_sync(~0u, s2, 2);
        q2 += __shfl_xor_sync(~0u, q2, 1); q2 += __shfl_xor_sync(~0u, q2, 2);
        if ((lane & 3) == 0) {
            int r1 = row0 + mi * 16;
            red[r1 * 4 + warp_n] = make_float2(s1, q1);
            red[(r1 + 8) * 4 + warp_n] = make_float2(s2, q2);
        }
    }
    __syncthreads();
#pragma unroll
    for (int mi = 0; mi < 4; ++mi) {
        int r1 = row0 + mi * 16;
        float s1 = 0, q1 = 0, s2 = 0, q2 = 0;
#pragma unroll
        for (int w = 0; w < 4; ++w) {
            float2 p1 = red[r1 * 4 + w];
            float2 p2 = red[(r1 + 8) * 4 + w];
            s1 += p1.x; q1 += p1.y;
            s2 += p2.x; q2 += p2.y;
        }
        float m1 = s1 * (1.0f / 128.0f);
        float rs1 = rsqrtf(q1 * (1.0f / 128.0f) - m1 * m1 + EPSm);
        float m2 = s2 * (1.0f / 128.0f);
        float rs2 = rsqrtf(q2 * (1.0f / 128.0f) - m2 * m2 + EPSm);
#pragma unroll
        for (int ni = 0; ni < 4; ++ni) {
            int col = col0 + ni * 8;
            float g0 = gs[col], g1 = gs[col + 1], bb0 = bs[col], bb1 = bs[col + 1];
            int r2 = r1 + 8;
            float f0 = (v[mi][ni][0] - m1) * rs1 * g0 + bb0;
            float f1 = (v[mi][ni][1] - m1) * rs1 * g1 + bb1;
            float f2 = (v[mi][ni][2] - m2) * rs2 * g0 + bb0;
            float f3 = (v[mi][ni][3] - m2) * rs2 * g1 + bb1;
            uint32_t h, l;
            uint32_t o1 = sw4(r1, col), o2 = sw4(r2, col);
            if (FP16) split2h(f0, f1, h, l); else split2(f0, f1, h, l);
            *reinterpret_cast<uint32_t*>(Ahi + o1) = h;
            *reinterpret_cast<uint32_t*>(Alo + o1) = l;
            if (FP16) split2h(f2, f3, h, l); else split2(f2, f3, h, l);
            *reinterpret_cast<uint32_t*>(Ahi + o2) = h;
            *reinterpret_cast<uint32_t*>(Alo + o2) = l;
        }
    }
    if (ENDSYNC) __syncthreads();
}

// ============================ kernels ============================

// Unified prologue: [0,1024) gram0 tiles, [1024,1056) QK, [1056,1632) weight prep
#define PREP_SMEM 71680
__global__ void __launch_bounds__(256, 1)
kprep_all(const float* __restrict__ xin,
          const float* __restrict__ lng, const float* __restrict__ lnb,
          const float* __restrict__ Qw, const float* __restrict__ Kw,
          const float* __restrict__ w1, const float* __restrict__ w2,
          const float* __restrict__ outw) {
    extern __shared__ char sm[];
    int b = blockIdx.x;
    int tid = threadIdx.x;

    if (b < 1024) {
        float* gs = reinterpret_cast<float*>(sm);
        float* bs = gs + 128;
        float2* red = reinterpret_cast<float2*>(sm + 1024);
        char* Hhi = sm + 6144;
        char* Hlo = sm + 6144 + 32768;
        uint32_t smb = smem_u32(sm);
        int lane = tid & 31, wid = tid >> 5;
        int warp_m = wid & 1, warp_n = wid >> 1;
        int row0 = warp_m * 64 + (lane >> 2);
        int col0 = warp_n * 32 + (lane & 3) * 2;
        if (tid < 128) { gs[tid] = lng[tid]; bs[tid] = lnb[tid]; }
        __syncthreads();

        const float* xt = xin + (size_t)b * 16384;
        float v[4][4][4];
#pragma unroll
        for (int mi = 0; mi < 4; ++mi)
#pragma unroll
            for (int ni = 0; ni < 4; ++ni) {
                const float* p = xt + (row0 + mi * 16) * 128 + col0 + ni * 8;
                float2 a = *reinterpret_cast<const float2*>(p);
                float2 bb = *reinterpret_cast<const float2*>(p + 8 * 128);
                v[mi][ni][0] = a.x; v[mi][ni][1] = a.y;
                v[mi][ni][2] = bb.x; v[mi][ni][3] = bb.y;
            }
        ln_acc<true, false>(v, gs, bs, Hhi, Hlo, red, warp_m, warp_n, lane, tid);

        float acc[4][4][4];
#pragma unroll
        for (int mi = 0; mi < 4; ++mi)
#pragma unroll
            for (int ni = 0; ni < 4; ++ni)
#pragma unroll
                for (int e = 0; e < 4; ++e) acc[mi][ni][e] = 0.f;
        mma_tt(acc, smb + 6144, smb + 6144 + 32768, warp_m, warp_n, lane);

        float* dst = g_part + (size_t)b * 16384;
#pragma unroll
        for (int mi = 0; mi < 4; ++mi)
#pragma unroll
            for (int ni = 0; ni < 4; ++ni) {
                int r1 = row0 + mi * 16, col = col0 + ni * 8;
                __stcs(reinterpret_cast<float2*>(dst + r1 * 128 + col),
                       make_float2(acc[mi][ni][0], acc[mi][ni][1]));
                __stcs(reinterpret_cast<float2*>(dst + (r1 + 8) * 128 + col),
                       make_float2(acc[mi][ni][2], acc[mi][ni][3]));
            }
    } else if (b < 1056) {
        float* Bs = reinterpret_cast<float*>(sm);          // [128][129]
        float* As = Bs + 128 * 129;                        // [4][128]
        for (int idx = tid; idx < 16384; idx += 256)
            Bs[(idx >> 7) * 129 + (idx & 127)] = Kw[idx];
        int r0 = (b - 1024) * 4;
        for (int idx = tid; idx < 512; idx += 256)
            As[idx] = Qw[(r0 + (idx >> 7)) * 128 + (idx & 127)];
        __syncthreads();
        int j = tid & 127, i0 = (tid >> 7) * 2;
        float c0 = 0.f, c1 = 0.f;
#pragma unroll 8
        for (int k = 0; k < 128; ++k) {
            float bb = Bs[j * 129 + k];
            c0 = fmaf(As[i0 * 128 + k], bb, c0);
            c1 = fmaf(As[i0 * 128 + 128 + k], bb, c1);
        }
        g_QK[(r0 + i0) * 128 + j] = c0;
        g_QK[(r0 + i0 + 1) * 128 + j] = c1;
    } else {
        int idx = (b - 1056) * 256 + tid;
        if (idx < 65536) {                 // w1h [512 n][128 k], single fp16
            int n = idx >> 7, k = idx & 127;
            g_w1h[idx] = __float2half(w1[k * 512 + n]);
        } else if (idx < 131072) {         // w2h [128 n][512 k], single fp16
            int j = idx - 65536;
            int n = j >> 9, k = j & 511;
            g_w2h[j] = __float2half(w2[k * 128 + n]);
        } else if (idx < 147456) {         // owt [128 n][128 k], bf16 hi/lo
            int j = idx - 131072;
            int n = j >> 7, k = j & 127;
            sp1(outw[k * 128 + n], &g_owt_hi[j], &g_owt_lo[j]);
        }
    }
}

// stage-1 reduce: 1024 partials -> 8 partials. 131072 threads, 128 loads each.
__global__ void kred1_kernel() {
    int idx = blockIdx.x * 256 + threadIdx.x;
    int e = idx & 16383;
    int g = idx >> 14;
    const float* p = g_part + (size_t)g * 128 * 16384 + e;
    float s0 = 0.f, s1 = 0.f, s2 = 0.f, s3 = 0.f;
#pragma unroll 8
    for (int i = 0; i < 128; i += 4) {
        s0 += __ldcs(p + (size_t)(i + 0) * 16384);
        s1 += __ldcs(p + (size_t)(i + 1) * 16384);
        s2 += __ldcs(p + (size_t)(i + 2) * 16384);
        s3 += __ldcs(p + (size_t)(i + 3) * 16384);
    }
    g_part2[(size_t)g * 16384 + e] = (s0 + s1) + (s2 + s3);
}

// fused mid kernel: T1 = G@Vw ; barrier ; Mt = split(QK @ T1)
#define TS_SMEM (128 * 129 * 4 + 512 * 4)
__global__ void __launch_bounds__(256, 1)
kmid_kernel(const float* __restrict__ Vw) {
    extern __shared__ float ts[];
    float* Bs = ts;
    float* As = ts + 128 * 129;
    int tid = threadIdx.x;
    int r0 = blockIdx.x * 4;
    int j = tid & 127, i0 = (tid >> 7) * 2;

    for (int idx = tid; idx < 16384; idx += 256)
        Bs[(idx >> 7) * 129 + (idx & 127)] = Vw[idx];
    for (int idx = tid; idx < 512; idx += 256) {
        int off = (r0 + (idx >> 7)) * 128 + (idx & 127);
        const float* p = g_part2 + off;
        float s = 0.f;
#pragma unroll
        for (int g = 0; g < 8; ++g) s += p[(size_t)g * 16384];
        As[idx] = s;
    }
    __syncthreads();
    {
        float c0 = 0.f, c1 = 0.f;
#pragma unroll 8
        for (int k = 0; k < 128; ++k) {
            float b = Bs[k * 129 + j];
            c0 = fmaf(As[i0 * 128 + k], b, c0);
            c1 = fmaf(As[i0 * 128 + 128 + k], b, c1);
        }
        g_T1[(r0 + i0) * 128 + j] = c0;
        g_T1[(r0 + i0 + 1) * 128 + j] = c1;
    }
    __threadfence();
    __syncthreads();
    if (tid == 0) {
        unsigned arrive = atomicAdd(&g_barrier, 1u);
        unsigned target = (arrive / 32u + 1u) * 32u;
        while (*reinterpret_cast<volatile unsigned*>(&g_barrier) < target)
            __nanosleep(64);
        __threadfence();
    }
    __syncthreads();
    for (int idx = tid; idx < 16384; idx += 256)
        Bs[(idx >> 7) * 129 + (idx & 127)] = __ldcg(g_T1 + idx);
    for (int idx = tid; idx < 512; idx += 256)
        As[idx] = g_QK[(r0 + (idx >> 7)) * 128 + (idx & 127)];
    __syncthreads();
    {
        float c0 = 0.f, c1 = 0.f;
#pragma unroll 8
        for (int k = 0; k < 128; ++k) {
            float b = Bs[k * 129 + j];
            c0 = fmaf(As[i0 * 128 + k], b, c0);
            c1 = fmaf(As[i0 * 128 + 128 + k], b, c1);
        }
        sp1(c0, &g_Mt_hi[j * 128 + r0 + i0], &g_Mt_lo[j * 128 + r0 + i0]);
        sp1(c1, &g_Mt_hi[j * 128 + r0 + i0 + 1], &g_Mt_lo[j * 128 + r0 + i0 + 1]);
    }
}

// ================= big fused kernel =================
#define KC_RED  5120
#define KC_A    10240                  // Ahi 32K | Alo 32K
#define KC_B0   (KC_A + 65536)         // 32K (attn Mt-hi / FF w1 single / owt-hi)
#define KC_B1   (KC_B0 + 32768)        // 32K (attn Mt-lo / FF w2 single / owt-lo)
#define KC_F    (KC_B1 + 32768)        // Fhi 16K | Flo 16K
#define KC_SMEM (KC_F + 32768)         // 174080

__global__ void __launch_bounds__(256, 1)
kc_mma(const float* __restrict__ xin, int srcIsG,
       const float* __restrict__ ln1g, const float* __restrict__ ln1b,
       const float* __restrict__ ln2g, const float* __restrict__ ln2b,
       const float* __restrict__ b1, const float* __restrict__ b2,
       const float* __restrict__ outb, float* __restrict__ outp, int last) {
    extern __shared__ char sm[];
    uint32_t smb = smem_u32(sm);
    int tid = threadIdx.x, lane = tid & 31, wid = tid >> 5;
    int warp_m = wid & 1, warp_n = wid >> 1;
    int row0 = warp_m * 64 + (lane >> 2);
    int col0 = warp_n * 32 + (lane & 3) * 2;

    float* ln1gs = reinterpret_cast<float*>(sm);
    float* ln1bs = ln1gs + 128;
    float* ln2gs = ln1gs + 256;
    float* ln2bs = ln1gs + 384;
    float* b2s   = ln1gs + 512;
    float* outbs = ln1gs + 640;
    float* b1s   = ln1gs + 768;     // 512 floats
    float2* red  = reinterpret_cast<float2*>(sm + KC_RED);
    if (tid < 128) {
        ln1gs[tid] = ln1g[tid]; ln1bs[tid] = ln1b[tid];
        ln2gs[tid] = ln2g[tid]; ln2bs[tid] = ln2b[tid];
        b2s[tid] = b2[tid]; outbs[tid] = outb[tid];
    }
    b1s[tid] = b1[tid]; b1s[tid + 256] = b1[tid + 256];

    // prefetch Mt (hi -> B0, lo -> B1)
    cp_tile256(smb + KC_B0, reinterpret_cast<const uint4*>(g_Mt_hi), 128, 16, tid);
    cp_tile256(smb + KC_B1, reinterpret_cast<const uint4*>(g_Mt_lo), 128, 16, tid);
    cpa_commit();

    // x in fragment layout
    size_t base = (size_t)blockIdx.x * 16384;
    const float* xt = (srcIsG ? g_x : xin) + base;
    float xr[4][4][4];
#pragma unroll
    for (int mi = 0; mi < 4; ++mi)
#pragma unroll
        for (int ni = 0; ni < 4; ++ni) {
            const float* p = xt + (row0 + mi * 16) * 128 + col0 + ni * 8;
            float2 a = *reinterpret_cast<const float2*>(p);
            float2 b = *reinterpret_cast<const float2*>(p + 8 * 128);
            xr[mi][ni][0] = a.x; xr[mi][ni][1] = a.y;
            xr[mi][ni][2] = b.x; xr[mi][ni][3] = b.y;
        }

    // A <- LN1(x), bf16 split
    ln_acc<false, false>(xr, ln1gs, ln1bs, sm + KC_A, sm + KC_A + 32768, red, warp_m, warp_n, lane, tid);
    cpa_wait<0>();
    __syncthreads();
    // x += h @ M  (bf16 3-split)
    mma_nt(xr, smb + KC_A, smb + KC_A + 32768, smb + KC_B0, smb + KC_B1, warp_m, warp_n, lane);
    __syncthreads();

    // prime FF pipeline: w1 sub-chunk 0 (single fp16, 16KB) -> B0
    cp_tile256(smb + KC_B0, reinterpret_cast<const uint4*>(g_w1h), 64, 16, tid);
    cpa_commit();

    // A <- LN2(x), fp16 split
    ln_acc<false, true>(xr, ln2gs, ln2bs, sm + KC_A, sm + KC_A + 32768, red, warp_m, warp_n, lane, tid);
    cpa_wait<0>();       // w1_0 landed
    __syncthreads();     // w1_0 + A visible

    // FF: 8 sub-chunks of 64 hidden units, fp16 2-split, 2 syncs/iter
#pragma unroll 1
    for (int c = 0; c < 8; ++c) {
        // prefetch w2_c (single fp16, 16KB) -> B1
        cp_tile128(smb + KC_B1, reinterpret_cast<const uint4*>(g_w2h) + c * 8, 64, tid);
        cpa_commit();
        float u[4][2][4];
#pragma unroll
        for (int mi = 0; mi < 4; ++mi)
#pragma unroll
            for (int ni = 0; ni < 2; ++ni)
#pragma unroll
                for (int e = 0; e < 4; ++e) u[mi][ni][e] = 0.f;
        mma_n64h(u, smb + KC_A, smb + KC_A + 32768, smb + KC_B0, warp_m, warp_n, lane);
        // bias + relu + fp16 split -> F
#pragma unroll
        for (int mi = 0; mi < 4; ++mi)
#pragma unroll
            for (int ni = 0; ni < 2; ++ni) {
                int hcol = warp_n * 16 + (lane & 3) * 2 + ni * 8;      // 0..63
                float bb0 = b1s[c * 64 + hcol], bb1 = b1s[c * 64 + hcol + 1];
                int r1 = row0 + mi * 16, r2 = r1 + 8;
                float f0 = fmaxf(u[mi][ni][0] + bb0, 0.f);
                float f1 = fmaxf(u[mi][ni][1] + bb1, 0.f);
                float f2 = fmaxf(u[mi][ni][2] + bb0, 0.f);
                float f3 = fmaxf(u[mi][ni][3] + bb1, 0.f);
                uint32_t h, l;
                uint32_t o1 = sw4_64(r1, hcol), o2 = sw4_64(r2, hcol);
                split2h(f0, f1, h, l);
                *reinterpret_cast<uint32_t*>(sm + KC_F + o1) = h;
                *reinterpret_cast<uint32_t*>(sm + KC_F + 16384 + o1) = l;
                split2h(f2, f3, h, l);
                *reinterpret_cast<uint32_t*>(sm + KC_F + o2) = h;
                *reinterpret_cast<uint32_t*>(sm + KC_F + 16384 + o2) = l;
            }
        cpa_wait<0>();       // w2_c landed
        __syncthreads();     // F + w2_c visible; B0 (w1_c) free
        if (c < 7) {
            cp_tile256(smb + KC_B0, reinterpret_cast<const uint4*>(g_w1h) + (c + 1) * 1024, 64, 16, tid);
        } else if (last) {
            cp_tile256(smb + KC_B0, reinterpret_cast<const uint4*>(g_owt_hi), 128, 16, tid);
        }
        cpa_commit();
        mma_k64h(xr, smb + KC_F, smb + KC_F + 16384, smb + KC_B1, warp_m, warp_n, lane);
        cpa_wait<0>();       // w1_{c+1} (or owt_hi) landed
        __syncthreads();     // B1/F free; next tile visible
    }

    // + b2
#pragma unroll
    for (int mi = 0; mi < 4; ++mi)
#pragma unroll
        for (int ni = 0; ni < 4; ++ni) {
            int col = col0 + ni * 8;
            xr[mi][ni][0] += b2s[col];     xr[mi][ni][1] += b2s[col + 1];
            xr[mi][ni][2] += b2s[col];     xr[mi][ni][3] += b2s[col + 1];
        }

    if (!last) {
        float* dst = g_x + base;
#pragma unroll
        for (int mi = 0; mi < 4; ++mi)
#pragma unroll
            for (int ni = 0; ni < 4; ++ni) {
                int r1 = row0 + mi * 16, col = col0 + ni * 8;
                *reinterpret_cast<float2*>(dst + r1 * 128 + col) =
                    make_float2(xr[mi][ni][0], xr[mi][ni][1]);
                *reinterpret_cast<float2*>(dst + (r1 + 8) * 128 + col) =
                    make_float2(xr[mi][ni][2], xr[mi][ni][3]);
            }
        // fused Gram partial for the NEXT step (bf16 split)
        ln_acc<true, false>(xr, ln1gs, ln1bs, sm + KC_A, sm + KC_A + 32768, red, warp_m, warp_n, lane, tid);
        float ga[4][4][4];
#pragma unroll
        for (int mi = 0; mi < 4; ++mi)
#pragma unroll
            for (int ni = 0; ni < 4; ++ni)
#pragma unroll
                for (int e = 0; e < 4; ++e) ga[mi][ni][e] = 0.f;
        mma_tt(ga, smb + KC_A, smb + KC_A + 32768, warp_m, warp_n, lane);
        float* pdst = g_part + (size_t)blockIdx.x * 16384;
#pragma unroll
        for (int mi = 0; mi < 4; ++mi)
#pragma unroll
            for (int ni = 0; ni < 4; ++ni) {
                int r1 = row0 + mi * 16, col = col0 + ni * 8;
                __stcs(reinterpret_cast<float2*>(pdst + r1 * 128 + col),
                       make_float2(ga[mi][ni][0], ga[mi][ni][1]));
                __stcs(reinterpret_cast<float2*>(pdst + (r1 + 8) * 128 + col),
                       make_float2(ga[mi][ni][2], ga[mi][ni][3]));
            }
    } else {
        // out = x @ outw + outb  (bf16 3-split; owt_hi already in B0)
        cp_tile256(smb + KC_B1, reinterpret_cast<const uint4*>(g_owt_lo), 128, 16, tid);
        cpa_commit();
#pragma unroll
        for (int mi = 0; mi < 4; ++mi)
#pragma unroll
            for (int ni = 0; ni < 4; ++ni) {
                int col = col0 + ni * 8;
                int r1 = row0 + mi * 16, r2 = r1 + 8;
                uint32_t h, l;
                uint32_t o1 = sw4(r1, col), o2 = sw4(r2, col);
                split2(xr[mi][ni][0], xr[mi][ni][1], h, l);
                *reinterpret_cast<uint32_t*>(sm + KC_A + o1) = h;
                *reinterpret_cast<uint32_t*>(sm + KC_A + 32768 + o1) = l;
                split2(xr[mi][ni][2], xr[mi][ni][3], h, l);
                *reinterpret_cast<uint32_t*>(sm + KC_A + o2) = h;
                *reinterpret_cast<uint32_t*>(sm + KC_A + 32768 + o2) = l;
            }
        cpa_wait<0>();
        __syncthreads();
        float o[4][4][4];
#pragma unroll
        for (int mi = 0; mi < 4; ++mi)
#pragma unroll
            for (int ni = 0; ni < 4; ++ni)
#pragma unroll
                for (int e = 0; e < 4; ++e) o[mi][ni][e] = 0.f;
        mma_nt(o, smb + KC_A, smb + KC_A + 32768, smb + KC_B0, smb + KC_B1, warp_m, warp_n, lane);
        float* dst = outp + base;
#pragma unroll
        for (int mi = 0; mi < 4; ++mi)
#pragma unroll
            for (int ni = 0; ni < 4; ++ni) {
                int r1 = row0 + mi * 16, col = col0 + ni * 8;
                *reinterpret_cast<float2*>(dst + r1 * 128 + col) =
                    make_float2(o[mi][ni][0] + outbs[col], o[mi][ni][1] + outbs[col + 1]);
                *reinterpret_cast<float2*>(dst + (r1 + 8) * 128 + col) =
                    make_float2(o[mi][ni][2] + outbs[col], o[mi][ni][3] + outbs[col + 1]);
            }
    }
}

// ============================ host launcher ============================
extern "C" void kernel_launch(void* const* d_in, const int* in_sizes, int n_in,
                              void* d_out, int out_size) {
    (void)in_sizes; (void)n_in; (void)out_size;
    const float* x    = (const float*)d_in[0];
    const float* Kw   = (const float*)d_in[1];
    const float* Qw   = (const float*)d_in[2];
    const float* Vw   = (const float*)d_in[3];
    const float* ln1g = (const float*)d_in[4];
    const float* ln1b = (const float*)d_in[5];
    const float* ln2g = (const float*)d_in[6];
    const float* ln2b = (const float*)d_in[7];
    const float* w1   = (const float*)d_in[8];
    const float* b1   = (const float*)d_in[9];
    const float* w2   = (const float*)d_in[10];
    const float* b2   = (const float*)d_in[11];
    const float* outw = (const float*)d_in[12];
    const float* outb = (const float*)d_in[13];
    float* out = (float*)d_out;

    cudaFuncSetAttribute(kc_mma, cudaFuncAttributeMaxDynamicSharedMemorySize, KC_SMEM);
    cudaFuncSetAttribute(kprep_all, cudaFuncAttributeMaxDynamicSharedMemorySize, PREP_SMEM);
    cudaFuncSetAttribute(kmid_kernel, cudaFuncAttributeMaxDynamicSharedMemorySize, TS_SMEM);

    kprep_all<<<1632, 256, PREP_SMEM>>>(x, ln1g, ln1b, Qw, Kw, w1, w2, outw);

    for (int t = 0; t < 4; ++t) {
        int srcIsG = (t != 0);
        kred1_kernel<<<512, 256>>>();                 // 1024 -> 8 partials
        kmid_kernel<<<32, 256, TS_SMEM>>>(Vw);        // T1 = G@Vw ; Mt = split(QK@T1)
        kc_mma<<<NTILESm, 256, KC_SMEM>>>(x, srcIsG, ln1g, ln1b, ln2g, ln2b,
                                          b1, b2, outb, out, t == 3);
    }
}

// round 17
// speedup vs baseline: 1.5082x; 1.2614x over previous
#include <cuda_runtime.h>
#include <cuda_bf16.h>
#include <cuda_fp16.h>
#include <cstdint>

#define EPSm   1e-5f
#define NROWSm 131072
#define NTILESm 1024
#define NPART  1024

// ---------------- device scratch ----------------
__device__ float g_x[NROWSm * 128];
__device__ float g_part[NPART * 128 * 128];   // 64 MB gram partials (stage 0)
__device__ float g_part2[8 * 128 * 128];      // 512 KB (stage 1)
__device__ float g_QK[128 * 128];
__device__ float g_T1[128 * 128];
__device__ unsigned g_barrier;                // monotonic ticket barrier for kmid
__device__ __nv_bfloat16 g_Mt_hi[128 * 128],  g_Mt_lo[128 * 128];   // attention (bf16 3-split)
__device__ __half g_w1h[512 * 128];           // FF weights, single fp16, [n][k]
__device__ __half g_w2h[128 * 512];           // [n][k]
__device__ __nv_bfloat16 g_owt_hi[128 * 128], g_owt_lo[128 * 128];  // out-proj (bf16 3-split)

// ---------------- helpers ----------------
__device__ __forceinline__ uint32_t smem_u32(const void* p) {
    uint32_t a;
    asm("{ .reg .u64 t; cvta.to.shared.u64 t, %1; cvt.u32.u64 %0, t; }" : "=r"(a) : "l"(p));
    return a;
}
// XOR-swizzled tile, 256B rows (128 x 2B cols)
__device__ __forceinline__ uint32_t sw16(int r, int c8) {
    return (uint32_t)(r * 256 + ((c8 ^ (r & 7)) << 4));
}
__device__ __forceinline__ uint32_t sw4(int r, int col) {
    return (uint32_t)(r * 256 + ((((col >> 3) ^ (r & 7)) << 4)) + (col & 7) * 2);
}
// XOR-swizzled tile, 128B rows (64 x 2B cols)
__device__ __forceinline__ uint32_t sw16_64(int r, int c8) {
    return (uint32_t)(r * 128 + ((((c8 ^ (r & 7)) & 7) << 4)));
}
__device__ __forceinline__ uint32_t sw4_64(int r, int col) {
    return (uint32_t)(r * 128 + ((((col >> 3) ^ (r & 7)) & 7) << 4) + (col & 7) * 2);
}
// bf16 hi/lo split (attention / gram / out-proj path)
__device__ __forceinline__ void split2(float f0, float f1, uint32_t& hi, uint32_t& lo) {
    __nv_bfloat162 H = __floats2bfloat162_rn(f0, f1);
    float r0 = f0 - __bfloat162float(H.x);
    float r1 = f1 - __bfloat162float(H.y);
    __nv_bfloat162 L = __floats2bfloat162_rn(r0, r1);
    hi = *reinterpret_cast<uint32_t*>(&H);
    lo = *reinterpret_cast<uint32_t*>(&L);
}
__device__ __forceinline__ uint32_t pack_h2(float f0, float f1) {
    __half2 H = __floats2half2_rn(f0, f1);
    return *reinterpret_cast<uint32_t*>(&H);
}
__device__ __forceinline__ void sp1(float v, __nv_bfloat16* h, __nv_bfloat16* l) {
    __nv_bfloat16 hh = __float2bfloat16(v);
    *h = hh;
    *l = __float2bfloat16(v - __bfloat162float(hh));
}
__device__ __forceinline__ void ldsm4(uint32_t* r, uint32_t a) {
    asm volatile("ldmatrix.sync.aligned.m8n8.x4.shared.b16 {%0,%1,%2,%3}, [%4];"
                 : "=r"(r[0]), "=r"(r[1]), "=r"(r[2]), "=r"(r[3]) : "r"(a));
}
__device__ __forceinline__ void ldsm2(uint32_t* r, uint32_t a) {
    asm volatile("ldmatrix.sync.aligned.m8n8.x2.shared.b16 {%0,%1}, [%2];"
                 : "=r"(r[0]), "=r"(r[1]) : "r"(a));
}
__device__ __forceinline__ void ldsm4t(uint32_t* r, uint32_t a) {
    asm volatile("ldmatrix.sync.aligned.m8n8.x4.trans.shared.b16 {%0,%1,%2,%3}, [%4];"
                 : "=r"(r[0]), "=r"(r[1]), "=r"(r[2]), "=r"(r[3]) : "r"(a));
}
__device__ __forceinline__ void ldsm2t(uint32_t* r, uint32_t a) {
    asm volatile("ldmatrix.sync.aligned.m8n8.x2.trans.shared.b16 {%0,%1}, [%2];"
                 : "=r"(r[0]), "=r"(r[1]) : "r"(a));
}
__device__ __forceinline__ void mma_bf16(float* c, const uint32_t* a, const uint32_t* b) {
    asm volatile(
        "mma.sync.aligned.m16n8k16.row.col.f32.bf16.bf16.f32 "
        "{%0,%1,%2,%3}, {%4,%5,%6,%7}, {%8,%9}, {%0,%1,%2,%3};"
        : "+f"(c[0]), "+f"(c[1]), "+f"(c[2]), "+f"(c[3])
        : "r"(a[0]), "r"(a[1]), "r"(a[2]), "r"(a[3]), "r"(b[0]), "r"(b[1]));
}
__device__ __forceinline__ void mma_f16(float* c, const uint32_t* a, const uint32_t* b) {
    asm volatile(
        "mma.sync.aligned.m16n8k16.row.col.f32.f16.f16.f32 "
        "{%0,%1,%2,%3}, {%4,%5,%6,%7}, {%8,%9}, {%0,%1,%2,%3};"
        : "+f"(c[0]), "+f"(c[1]), "+f"(c[2]), "+f"(c[3])
        : "r"(a[0]), "r"(a[1]), "r"(a[2]), "r"(a[3]), "r"(b[0]), "r"(b[1]));
}
// ---- cp.async ----
__device__ __forceinline__ void cpa16(uint32_t dst, const void* src) {
    asm volatile("cp.async.cg.shared.global [%0], [%1], 16;" :: "r"(dst), "l"(src));
}
__device__ __forceinline__ void cpa_commit() { asm volatile("cp.async.commit_group;"); }
template<int N> __device__ __forceinline__ void cpa_wait() {
    asm volatile("cp.async.wait_group %0;" :: "n"(N));
}
// nrows x 256B swizzled tile via cp.async (256 threads)
__device__ __forceinline__ void cp_tile256(uint32_t dst, const uint4* __restrict__ src,
                                           int nrows, int rs_u4, int tid) {
    int n = nrows * 16;
    for (int idx = tid; idx < n; idx += 256) {
        int r = idx >> 4, c8 = idx & 15;
        cpa16(dst + sw16(r, c8), src + r * rs_u4 + c8);
    }
}
// 128 rows x 128B swizzled tile via cp.async
__device__ __forceinline__ void cp_tile128(uint32_t dst, const uint4* __restrict__ src,
                                           int rs_u4, int tid) {
#pragma unroll
    for (int i = 0; i < 4; ++i) {
        int idx = tid + i * 256;
        int r = idx >> 3, c8 = idx & 7;
        cpa16(dst + sw16_64(r, c8), src + r * rs_u4 + c8);
    }
}

// C[128][128] += A(128x128k) @ Bt(128n x 128k)^T, bf16 3-split (256B-row tiles)
__device__ __forceinline__ void mma_nt(float (&acc)[4][4][4],
                                       uint32_t aHi, uint32_t aLo,
                                       uint32_t bHi, uint32_t bLo,
                                       int warp_m, int warp_n, int lane) {
#pragma unroll
    for (int k8 = 0; k8 < 8; ++k8) {
        uint32_t aH[4][4], aL[4][4], bH[4][2], bL[4][2];
        int ar = warp_m * 64 + (lane & 15);
        int ac8 = k8 * 2 + (lane >> 4);
#pragma unroll
        for (int mi = 0; mi < 4; ++mi) {
            uint32_t off = sw16(ar + mi * 16, ac8);
            ldsm4(aH[mi], aHi + off);
            ldsm4(aL[mi], aLo + off);
        }
        int l15 = lane & 15;
        int br = warp_n * 32 + (l15 & 7);
        int bc8 = k8 * 2 + (l15 >> 3);
#pragma unroll
        for (int ni = 0; ni < 4; ++ni) {
            uint32_t off = sw16(br + ni * 8, bc8);
            ldsm2(bH[ni], bHi + off);
            ldsm2(bL[ni], bLo + off);
        }
#pragma unroll
        for (int mi = 0; mi < 4; ++mi)
#pragma unroll
            for (int ni = 0; ni < 4; ++ni) {
                mma_bf16(acc[mi][ni], aH[mi], bH[ni]);
                mma_bf16(acc[mi][ni], aH[mi], bL[ni]);
                mma_bf16(acc[mi][ni], aL[mi], bH[ni]);
            }
    }
}

// FF GEMM1 (all single fp16): u[128][64] = A(128x128k) @ w1(64n x 128k)^T
__device__ __forceinline__ void mma_n64s(float (&u)[4][2][4],
                                         uint32_t aS, uint32_t bS,
                                         int warp_m, int warp_n, int lane) {
#pragma unroll
    for (int k8 = 0; k8 < 8; ++k8) {
        uint32_t aF[4][4], bF[2][2];
        int ar = warp_m * 64 + (lane & 15);
        int ac8 = k8 * 2 + (lane >> 4);
#pragma unroll
        for (int mi = 0; mi < 4; ++mi)
            ldsm4(aF[mi], aS + sw16(ar + mi * 16, ac8));
        int l15 = lane & 15;
        int br = warp_n * 16 + (l15 & 7);
        int bc8 = k8 * 2 + (l15 >> 3);
#pragma unroll
        for (int ni = 0; ni < 2; ++ni)
            ldsm2(bF[ni], bS + sw16(br + ni * 8, bc8));
#pragma unroll
        for (int mi = 0; mi < 4; ++mi)
#pragma unroll
            for (int ni = 0; ni < 2; ++ni)
                mma_f16(u[mi][ni], aF[mi], bF[ni]);
    }
}

// FF GEMM2 (all single fp16): C += F(128m x 64k) @ w2(128n x 64k)^T (128B rows)
__device__ __forceinline__ void mma_k64s(float (&acc)[4][4][4],
                                         uint32_t fS, uint32_t bS,
                                         int warp_m, int warp_n, int lane) {
#pragma unroll
    for (int k8 = 0; k8 < 4; ++k8) {
        uint32_t aF[4][4], bF[4][2];
        int ar = warp_m * 64 + (lane & 15);
        int ac8 = k8 * 2 + (lane >> 4);
#pragma unroll
        for (int mi = 0; mi < 4; ++mi)
            ldsm4(aF[mi], fS + sw16_64(ar + mi * 16, ac8));
        int l15 = lane & 15;
        int br = warp_n * 32 + (l15 & 7);
        int bc8 = k8 * 2 + (l15 >> 3);
#pragma unroll
        for (int ni = 0; ni < 4; ++ni)
            ldsm2(bF[ni], bS + sw16_64(br + ni * 8, bc8));
#pragma unroll
        for (int mi = 0; mi < 4; ++mi)
#pragma unroll
            for (int ni = 0; ni < 4; ++ni)
                mma_f16(acc[mi][ni], aF[mi], bF[ni]);
    }
}

// Gram: C += H^T @ H, bf16 3-split; trans loads of row-major H tile.
__device__ __forceinline__ void mma_tt(float (&acc)[4][4][4],
                                       uint32_t hHi, uint32_t hLo,
                                       int warp_m, int warp_n, int lane) {
#pragma unroll
    for (int k8 = 0; k8 < 8; ++k8) {
        int k0 = k8 * 16;
        uint32_t aH[4][4], aL[4][4], bH[4][2], bL[4][2];
        int ar = k0 + (lane & 7) + ((lane >> 4) << 3);
        int asel = (lane >> 3) & 1;
#pragma unroll
        for (int mi = 0; mi < 4; ++mi) {
            int c8 = ((warp_m * 64 + mi * 16) >> 3) + asel;
            uint32_t off = sw16(ar, c8);
            ldsm4t(aH[mi], hHi + off);
            ldsm4t(aL[mi], hLo + off);
        }
        int l15 = lane & 15;
        int br = k0 + (l15 & 7) + ((l15 >> 3) << 3);
#pragma unroll
        for (int ni = 0; ni < 4; ++ni) {
            int c8 = (warp_n * 32 + ni * 8) >> 3;
            uint32_t off = sw16(br, c8);
            ldsm2t(bH[ni], hHi + off);
            ldsm2t(bL[ni], hLo + off);
        }
#pragma unroll
        for (int mi = 0; mi < 4; ++mi)
#pragma unroll
            for (int ni = 0; ni < 4; ++ni) {
                mma_bf16(acc[mi][ni], aH[mi], bH[ni]);
                mma_bf16(acc[mi][ni], aH[mi], bL[ni]);
                mma_bf16(acc[mi][ni], aL[mi], bH[ni]);
            }
    }
}

// LayerNorm of fragment-layout values -> swizzled 256B-row tile.
// MODE 0: bf16 hi/lo split (writes Ahi+Alo). MODE 1: single fp16 (writes Ahi only).
template<bool ENDSYNC, int MODE>
__device__ __forceinline__ void ln_acc(const float (&v)[4][4][4],
                                       const float* gs, const float* bs,
                                       char* Ahi, char* Alo,
                                       float2* red,
                                       int warp_m, int warp_n, int lane, int tid) {
    int row0 = warp_m * 64 + (lane >> 2);
    int col0 = warp_n * 32 + (lane & 3) * 2;
#pragma unroll
    for (int mi = 0; mi < 4; ++mi) {
        float s1 = 0, q1 = 0, s2 = 0, q2 = 0;
#pragma unroll
        for (int ni = 0; ni < 4; ++ni) {
            s1 += v[mi][ni][0] + v[mi][ni][1];
            q1 += v[mi][ni][0] * v[mi][ni][0] + v[mi][ni][1] * v[mi][ni][1];
            s2 += v[mi][ni][2] + v[mi][ni][3];
            q2 += v[mi][ni][2] * v[mi][ni][2] + v[mi][ni][3] * v[mi][ni][3];
        }
        s1 += __shfl_xor_sync(~0u, s1, 1); s1 += __shfl_xor_sync(~0u, s1, 2);
        q1 += __shfl_xor_sync(~0u, q1, 1); q1 += __shfl_xor_sync(~0u, q1, 2);
        s2 += __shfl_xor_sync(~0u, s2, 1); s2 += __shfl_xor_sync(~0u, s2, 2);
        q2 += __shfl_xor_sync(~0u, q2, 1); q2 += __shfl_xor_sync(~0u, q2, 2);
        if ((lane & 3) == 0) {
            int r1 = row0 + mi * 16;
            red[r1 * 4 + warp_n] = make_float2(s1, q1);
            red[(r1 + 8) * 4 + warp_n] = make_float2(s2, q2);
        }
    }
    __syncthreads();
#pragma unroll
    for (int mi = 0; mi < 4; ++mi) {
        int r1 = row0 + mi * 16;
        float s1 = 0, q1 = 0, s2 = 0, q2 = 0;
#pragma unroll
        for (int w = 0; w < 4; ++w) {
            float2 p1 = red[r1 * 4 + w];
            float2 p2 = red[(r1 + 8) * 4 + w];
            s1 += p1.x; q1 += p1.y;
            s2 += p2.x; q2 += p2.y;
        }
        float m1 = s1 * (1.0f / 128.0f);
        float rs1 = rsqrtf(q1 * (1.0f / 128.0f) - m1 * m1 + EPSm);
        float m2 = s2 * (1.0f / 128.0f);
        float rs2 = rsqrtf(q2 * (1.0f / 128.0f) - m2 * m2 + EPSm);
#pragma unroll
        for (int ni = 0; ni < 4; ++ni) {
            int col = col0 + ni * 8;
            float g0 = gs[col], g1 = gs[col + 1], bb0 = bs[col], bb1 = bs[col + 1];
            int r2 = r1 + 8;
            float f0 = (v[mi][ni][0] - m1) * rs1 * g0 + bb0;
            float f1 = (v[mi][ni][1] - m1) * rs1 * g1 + bb1;
            float f2 = (v[mi][ni][2] - m2) * rs2 * g0 + bb0;
            float f3 = (v[mi][ni][3] - m2) * rs2 * g1 + bb1;
            uint32_t o1 = sw4(r1, col), o2 = sw4(r2, col);
            if (MODE == 0) {
                uint32_t h, l;
                split2(f0, f1, h, l);
                *reinterpret_cast<uint32_t*>(Ahi + o1) = h;
                *reinterpret_cast<uint32_t*>(Alo + o1) = l;
                split2(f2, f3, h, l);
                *reinterpret_cast<uint32_t*>(Ahi + o2) = h;
                *reinterpret_cast<uint32_t*>(Alo + o2) = l;
            } else {
                *reinterpret_cast<uint32_t*>(Ahi + o1) = pack_h2(f0, f1);
                *reinterpret_cast<uint32_t*>(Ahi + o2) = pack_h2(f2, f3);
            }
        }
    }
    if (ENDSYNC) __syncthreads();
}

// ============================ kernels ============================

// Unified prologue: [0,1024) gram0 tiles, [1024,1056) QK, [1056,1632) weight prep
#define PREP_SMEM 71680
__global__ void __launch_bounds__(256, 1)
kprep_all(const float* __restrict__ xin,
          const float* __restrict__ lng, const float* __restrict__ lnb,
          const float* __restrict__ Qw, const float* __restrict__ Kw,
          const float* __restrict__ w1, const float* __restrict__ w2,
          const float* __restrict__ outw) {
    extern __shared__ char sm[];
    int b = blockIdx.x;
    int tid = threadIdx.x;

    if (b < 1024) {
        float* gs = reinterpret_cast<float*>(sm);
        float* bs = gs + 128;
        float2* red = reinterpret_cast<float2*>(sm + 1024);
        char* Hhi = sm + 6144;
        char* Hlo = sm + 6144 + 32768;
        uint32_t smb = smem_u32(sm);
        int lane = tid & 31, wid = tid >> 5;
        int warp_m = wid & 1, warp_n = wid >> 1;
        int row0 = warp_m * 64 + (lane >> 2);
        int col0 = warp_n * 32 + (lane & 3) * 2;
        if (tid < 128) { gs[tid] = lng[tid]; bs[tid] = lnb[tid]; }
        __syncthreads();

        const float* xt = xin + (size_t)b * 16384;
        float v[4][4][4];
#pragma unroll
        for (int mi = 0; mi < 4; ++mi)
#pragma unroll
            for (int ni = 0; ni < 4; ++ni) {
                const float* p = xt + (row0 + mi * 16) * 128 + col0 + ni * 8;
                float2 a = *reinterpret_cast<const float2*>(p);
                float2 bb = *reinterpret_cast<const float2*>(p + 8 * 128);
                v[mi][ni][0] = a.x; v[mi][ni][1] = a.y;
                v[mi][ni][2] = bb.x; v[mi][ni][3] = bb.y;
            }
        ln_acc<true, 0>(v, gs, bs, Hhi, Hlo, red, warp_m, warp_n, lane, tid);

        float acc[4][4][4];
#pragma unroll
        for (int mi = 0; mi < 4; ++mi)
#pragma unroll
            for (int ni = 0; ni < 4; ++ni)
#pragma unroll
                for (int e = 0; e < 4; ++e) acc[mi][ni][e] = 0.f;
        mma_tt(acc, smb + 6144, smb + 6144 + 32768, warp_m, warp_n, lane);

        float* dst = g_part + (size_t)b * 16384;
#pragma unroll
        for (int mi = 0; mi < 4; ++mi)
#pragma unroll
            for (int ni = 0; ni < 4; ++ni) {
                int r1 = row0 + mi * 16, col = col0 + ni * 8;
                __stcs(reinterpret_cast<float2*>(dst + r1 * 128 + col),
                       make_float2(acc[mi][ni][0], acc[mi][ni][1]));
                __stcs(reinterpret_cast<float2*>(dst + (r1 + 8) * 128 + col),
                       make_float2(acc[mi][ni][2], acc[mi][ni][3]));
            }
    } else if (b < 1056) {
        float* Bs = reinterpret_cast<float*>(sm);          // [128][129]
        float* As = Bs + 128 * 129;                        // [4][128]
        for (int idx = tid; idx < 16384; idx += 256)
            Bs[(idx >> 7) * 129 + (idx & 127)] = Kw[idx];
        int r0 = (b - 1024) * 4;
        for (int idx = tid; idx < 512; idx += 256)
            As[idx] = Qw[(r0 + (idx >> 7)) * 128 + (idx & 127)];
        __syncthreads();
        int j = tid & 127, i0 = (tid >> 7) * 2;
        float c0 = 0.f, c1 = 0.f;
#pragma unroll 8
        for (int k = 0; k < 128; ++k) {
            float bb = Bs[j * 129 + k];
            c0 = fmaf(As[i0 * 128 + k], bb, c0);
            c1 = fmaf(As[i0 * 128 + 128 + k], bb, c1);
        }
        g_QK[(r0 + i0) * 128 + j] = c0;
        g_QK[(r0 + i0 + 1) * 128 + j] = c1;
    } else {
        int idx = (b - 1056) * 256 + tid;
        if (idx < 65536) {                 // w1h [512 n][128 k], single fp16
            int n = idx >> 7, k = idx & 127;
            g_w1h[idx] = __float2half(w1[k * 512 + n]);
        } else if (idx < 131072) {         // w2h [128 n][512 k], single fp16
            int j = idx - 65536;
            int n = j >> 9, k = j & 511;
            g_w2h[j] = __float2half(w2[k * 128 + n]);
        } else if (idx < 147456) {         // owt [128 n][128 k], bf16 hi/lo
            int j = idx - 131072;
            int n = j >> 7, k = j & 127;
            sp1(outw[k * 128 + n], &g_owt_hi[j], &g_owt_lo[j]);
        }
    }
}

// stage-1 reduce: 1024 partials -> 8 partials. 131072 threads, 128 loads each.
__global__ void kred1_kernel() {
    int idx = blockIdx.x * 256 + threadIdx.x;
    int e = idx & 16383;
    int g = idx >> 14;
    const float* p = g_part + (size_t)g * 128 * 16384 + e;
    float s0 = 0.f, s1 = 0.f, s2 = 0.f, s3 = 0.f;
#pragma unroll 8
    for (int i = 0; i < 128; i += 4) {
        s0 += __ldcs(p + (size_t)(i + 0) * 16384);
        s1 += __ldcs(p + (size_t)(i + 1) * 16384);
        s2 += __ldcs(p + (size_t)(i + 2) * 16384);
        s3 += __ldcs(p + (size_t)(i + 3) * 16384);
    }
    g_part2[(size_t)g * 16384 + e] = (s0 + s1) + (s2 + s3);
}

// fused mid kernel: T1 = G@Vw ; barrier ; Mt = split(QK @ T1)
#define TS_SMEM (128 * 129 * 4 + 512 * 4)
__global__ void __launch_bounds__(256, 1)
kmid_kernel(const float* __restrict__ Vw) {
    extern __shared__ float ts[];
    float* Bs = ts;
    float* As = ts + 128 * 129;
    int tid = threadIdx.x;
    int r0 = blockIdx.x * 4;
    int j = tid & 127, i0 = (tid >> 7) * 2;

    for (int idx = tid; idx < 16384; idx += 256)
        Bs[(idx >> 7) * 129 + (idx & 127)] = Vw[idx];
    for (int idx = tid; idx < 512; idx += 256) {
        int off = (r0 + (idx >> 7)) * 128 + (idx & 127);
        const float* p = g_part2 + off;
        float s = 0.f;
#pragma unroll
        for (int g = 0; g < 8; ++g) s += p[(size_t)g * 16384];
        As[idx] = s;
    }
    __syncthreads();
    {
        float c0 = 0.f, c1 = 0.f;
#pragma unroll 8
        for (int k = 0; k < 128; ++k) {
            float b = Bs[k * 129 + j];
            c0 = fmaf(As[i0 * 128 + k], b, c0);
            c1 = fmaf(As[i0 * 128 + 128 + k], b, c1);
        }
        g_T1[(r0 + i0) * 128 + j] = c0;
        g_T1[(r0 + i0 + 1) * 128 + j] = c1;
    }
    __threadfence();
    __syncthreads();
    if (tid == 0) {
        unsigned arrive = atomicAdd(&g_barrier, 1u);
        unsigned target = (arrive / 32u + 1u) * 32u;
        while (*reinterpret_cast<volatile unsigned*>(&g_barrier) < target)
            __nanosleep(64);
        __threadfence();
    }
    __syncthreads();
    for (int idx = tid; idx < 16384; idx += 256)
        Bs[(idx >> 7) * 129 + (idx & 127)] = __ldcg(g_T1 + idx);
    for (int idx = tid; idx < 512; idx += 256)
        As[idx] = g_QK[(r0 + (idx >> 7)) * 128 + (idx & 127)];
    __syncthreads();
    {
        float c0 = 0.f, c1 = 0.f;
#pragma unroll 8
        for (int k = 0; k < 128; ++k) {
            float b = Bs[k * 129 + j];
            c0 = fmaf(As[i0 * 128 + k], b, c0);
            c1 = fmaf(As[i0 * 128 + 128 + k], b, c1);
        }
        sp1(c0, &g_Mt_hi[j * 128 + r0 + i0], &g_Mt_lo[j * 128 + r0 + i0]);
        sp1(c1, &g_Mt_hi[j * 128 + r0 + i0 + 1], &g_Mt_lo[j * 128 + r0 + i0 + 1]);
    }
}

// ================= big fused kernel =================
#define KC_RED  5120
#define KC_A    10240                  // Ahi 32K | Alo 32K
#define KC_B0   (KC_A + 65536)         // 32K (attn Mt-hi / FF w1 single / owt-hi)
#define KC_B1   (KC_B0 + 32768)        // 32K (attn Mt-lo / FF w2 single / owt-lo)
#define KC_F    (KC_B1 + 32768)        // F single fp16, 16K
#define KC_SMEM (KC_F + 32768)         // 174080

__global__ void __launch_bounds__(256, 1)
kc_mma(const float* __restrict__ xin, int srcIsG,
       const float* __restrict__ ln1g, const float* __restrict__ ln1b,
       const float* __restrict__ ln2g, const float* __restrict__ ln2b,
       const float* __restrict__ b1, const float* __restrict__ b2,
       const float* __restrict__ outb, float* __restrict__ outp, int last) {
    extern __shared__ char sm[];
    uint32_t smb = smem_u32(sm);
    int tid = threadIdx.x, lane = tid & 31, wid = tid >> 5;
    int warp_m = wid & 1, warp_n = wid >> 1;
    int row0 = warp_m * 64 + (lane >> 2);
    int col0 = warp_n * 32 + (lane & 3) * 2;

    float* ln1gs = reinterpret_cast<float*>(sm);
    float* ln1bs = ln1gs + 128;
    float* ln2gs = ln1gs + 256;
    float* ln2bs = ln1gs + 384;
    float* b2s   = ln1gs + 512;
    float* outbs = ln1gs + 640;
    float* b1s   = ln1gs + 768;     // 512 floats
    float2* red  = reinterpret_cast<float2*>(sm + KC_RED);
    if (tid < 128) {
        ln1gs[tid] = ln1g[tid]; ln1bs[tid] = ln1b[tid];
        ln2gs[tid] = ln2g[tid]; ln2bs[tid] = ln2b[tid];
        b2s[tid] = b2[tid]; outbs[tid] = outb[tid];
    }
    b1s[tid] = b1[tid]; b1s[tid + 256] = b1[tid + 256];

    // prefetch Mt (hi -> B0, lo -> B1)
    cp_tile256(smb + KC_B0, reinterpret_cast<const uint4*>(g_Mt_hi), 128, 16, tid);
    cp_tile256(smb + KC_B1, reinterpret_cast<const uint4*>(g_Mt_lo), 128, 16, tid);
    cpa_commit();

    // x in fragment layout
    size_t base = (size_t)blockIdx.x * 16384;
    const float* xt = (srcIsG ? g_x : xin) + base;
    float xr[4][4][4];
#pragma unroll
    for (int mi = 0; mi < 4; ++mi)
#pragma unroll
        for (int ni = 0; ni < 4; ++ni) {
            const float* p = xt + (row0 + mi * 16) * 128 + col0 + ni * 8;
            float2 a = *reinterpret_cast<const float2*>(p);
            float2 b = *reinterpret_cast<const float2*>(p + 8 * 128);
            xr[mi][ni][0] = a.x; xr[mi][ni][1] = a.y;
            xr[mi][ni][2] = b.x; xr[mi][ni][3] = b.y;
        }

    // A <- LN1(x), bf16 split
    ln_acc<false, 0>(xr, ln1gs, ln1bs, sm + KC_A, sm + KC_A + 32768, red, warp_m, warp_n, lane, tid);
    cpa_wait<0>();
    __syncthreads();
    // x += h @ M  (bf16 3-split)
    mma_nt(xr, smb + KC_A, smb + KC_A + 32768, smb + KC_B0, smb + KC_B1, warp_m, warp_n, lane);
    __syncthreads();

    // prime FF pipeline: w1 sub-chunk 0 (single fp16, 16KB) -> B0
    cp_tile256(smb + KC_B0, reinterpret_cast<const uint4*>(g_w1h), 64, 16, tid);
    cpa_commit();

    // A <- LN2(x), single fp16
    ln_acc<false, 1>(xr, ln2gs, ln2bs, sm + KC_A, sm + KC_A + 32768, red, warp_m, warp_n, lane, tid);
    cpa_wait<0>();       // w1_0 landed
    __syncthreads();     // w1_0 + A visible

    // FF: 8 sub-chunks of 64 hidden units, all single fp16, 2 syncs/iter
#pragma unroll 1
    for (int c = 0; c < 8; ++c) {
        // prefetch w2_c (single fp16, 16KB) -> B1
        cp_tile128(smb + KC_B1, reinterpret_cast<const uint4*>(g_w2h) + c * 8, 64, tid);
        cpa_commit();
        float u[4][2][4];
#pragma unroll
        for (int mi = 0; mi < 4; ++mi)
#pragma unroll
            for (int ni = 0; ni < 2; ++ni)
#pragma unroll
                for (int e = 0; e < 4; ++e) u[mi][ni][e] = 0.f;
        mma_n64s(u, smb + KC_A, smb + KC_B0, warp_m, warp_n, lane);
        // bias + relu + single fp16 -> F
#pragma unroll
        for (int mi = 0; mi < 4; ++mi)
#pragma unroll
            for (int ni = 0; ni < 2; ++ni) {
                int hcol = warp_n * 16 + (lane & 3) * 2 + ni * 8;      // 0..63
                float bb0 = b1s[c * 64 + hcol], bb1 = b1s[c * 64 + hcol + 1];
                int r1 = row0 + mi * 16, r2 = r1 + 8;
                float f0 = fmaxf(u[mi][ni][0] + bb0, 0.f);
                float f1 = fmaxf(u[mi][ni][1] + bb1, 0.f);
                float f2 = fmaxf(u[mi][ni][2] + bb0, 0.f);
                float f3 = fmaxf(u[mi][ni][3] + bb1, 0.f);
                *reinterpret_cast<uint32_t*>(sm + KC_F + sw4_64(r1, hcol)) = pack_h2(f0, f1);
                *reinterpret_cast<uint32_t*>(sm + KC_F + sw4_64(r2, hcol)) = pack_h2(f2, f3);
            }
        cpa_wait<0>();       // w2_c landed
        __syncthreads();     // F + w2_c visible; B0 (w1_c) free
        if (c < 7) {
            cp_tile256(smb + KC_B0, reinterpret_cast<const uint4*>(g_w1h) + (c + 1) * 1024, 64, 16, tid);
        } else if (last) {
            cp_tile256(smb + KC_B0, reinterpret_cast<const uint4*>(g_owt_hi), 128, 16, tid);
        }
        cpa_commit();
        mma_k64s(xr, smb + KC_F, smb + KC_B1, warp_m, warp_n, lane);
        cpa_wait<0>();       // w1_{c+1} (or owt_hi) landed
        __syncthreads();     // B1/F free; next tile visible
    }

    // + b2
#pragma unroll
    for (int mi = 0; mi < 4; ++mi)
#pragma unroll
        for (int ni = 0; ni < 4; ++ni) {
            int col = col0 + ni * 8;
            xr[mi][ni][0] += b2s[col];     xr[mi][ni][1] += b2s[col + 1];
            xr[mi][ni][2] += b2s[col];     xr[mi][ni][3] += b2s[col + 1];
        }

    if (!last) {
        float* dst = g_x + base;
#pragma unroll
        for (int mi = 0; mi < 4; ++mi)
#pragma unroll
            for (int ni = 0; ni < 4; ++ni) {
                int r1 = row0 + mi * 16, col = col0 + ni * 8;
                *reinterpret_cast<float2*>(dst + r1 * 128 + col) =
                    make_float2(xr[mi][ni][0], xr[mi][ni][1]);
                *reinterpret_cast<float2*>(dst + (r1 + 8) * 128 + col) =
                    make_float2(xr[mi][ni][2], xr[mi][ni][3]);
            }
        // fused Gram partial for the NEXT step (bf16 split)
        ln_acc<true, 0>(xr, ln1gs, ln1bs, sm + KC_A, sm + KC_A + 32768, red, warp_m, warp_n, lane, tid);
        float ga[4][4][4];
#pragma unroll
        for (int mi = 0; mi < 4; ++mi)
#pragma unroll
            for (int ni = 0; ni < 4; ++ni)
#pragma unroll
                for (int e = 0; e < 4; ++e) ga[mi][ni][e] = 0.f;
        mma_tt(ga, smb + KC_A, smb + KC_A + 32768, warp_m, warp_n, lane);
        float* pdst = g_part + (size_t)blockIdx.x * 16384;
#pragma unroll
        for (int mi = 0; mi < 4; ++mi)
#pragma unroll
            for (int ni = 0; ni < 4; ++ni) {
                int r1 = row0 + mi * 16, col = col0 + ni * 8;
                __stcs(reinterpret_cast<float2*>(pdst + r1 * 128 + col),
                       make_float2(ga[mi][ni][0], ga[mi][ni][1]));
                __stcs(reinterpret_cast<float2*>(pdst + (r1 + 8) * 128 + col),
                       make_float2(ga[mi][ni][2], ga[mi][ni][3]));
            }
    } else {
        // out = x @ outw + outb  (bf16 3-split; owt_hi already in B0)
        cp_tile256(smb + KC_B1, reinterpret_cast<const uint4*>(g_owt_lo), 128, 16, tid);
        cpa_commit();
#pragma unroll
        for (int mi = 0; mi < 4; ++mi)
#pragma unroll
            for (int ni = 0; ni < 4; ++ni) {
                int col = col0 + ni * 8;
                int r1 = row0 + mi * 16, r2 = r1 + 8;
                uint32_t h, l;
                uint32_t o1 = sw4(r1, col), o2 = sw4(r2, col);
                split2(xr[mi][ni][0], xr[mi][ni][1], h, l);
                *reinterpret_cast<uint32_t*>(sm + KC_A + o1) = h;
                *reinterpret_cast<uint32_t*>(sm + KC_A + 32768 + o1) = l;
                split2(xr[mi][ni][2], xr[mi][ni][3], h, l);
                *reinterpret_cast<uint32_t*>(sm + KC_A + o2) = h;
                *reinterpret_cast<uint32_t*>(sm + KC_A + 32768 + o2) = l;
            }
        cpa_wait<0>();
        __syncthreads();
        float o[4][4][4];
#pragma unroll
        for (int mi = 0; mi < 4; ++mi)
#pragma unroll
            for (int ni = 0; ni < 4; ++ni)
#pragma unroll
                for (int e = 0; e < 4; ++e) o[mi][ni][e] = 0.f;
        mma_nt(o, smb + KC_A, smb + KC_A + 32768, smb + KC_B0, smb + KC_B1, warp_m, warp_n, lane);
        float* dst = outp + base;
#pragma unroll
        for (int mi = 0; mi < 4; ++mi)
#pragma unroll
            for (int ni = 0; ni < 4; ++ni) {
                int r1 = row0 + mi * 16, col = col0 + ni * 8;
                *reinterpret_cast<float2*>(dst + r1 * 128 + col) =
                    make_float2(o[mi][ni][0] + outbs[col], o[mi][ni][1] + outbs[col + 1]);
                *reinterpret_cast<float2*>(dst + (r1 + 8) * 128 + col) =
                    make_float2(o[mi][ni][2] + outbs[col], o[mi][ni][3] + outbs[col + 1]);
            }
    }
}

// ============================ host launcher ============================
extern "C" void kernel_launch(void* const* d_in, const int* in_sizes, int n_in,
                              void* d_out, int out_size) {
    (void)in_sizes; (void)n_in; (void)out_size;
    const float* x    = (const float*)d_in[0];
    const float* Kw   = (const float*)d_in[1];
    const float* Qw   = (const float*)d_in[2];
    const float* Vw   = (const float*)d_in[3];
    const float* ln1g = (const float*)d_in[4];
    const float* ln1b = (const float*)d_in[5];
    const float* ln2g = (const float*)d_in[6];
    const float* ln2b = (const float*)d_in[7];
    const float* w1   = (const float*)d_in[8];
    const float* b1   = (const float*)d_in[9];
    const float* w2   = (const float*)d_in[10];
    const float* b2   = (const float*)d_in[11];
    const float* outw = (const float*)d_in[12];
    const float* outb = (const float*)d_in[13];
    float* out = (float*)d_out;

    cudaFuncSetAttribute(kc_mma, cudaFuncAttributeMaxDynamicSharedMemorySize, KC_SMEM);
    cudaFuncSetAttribute(kprep_all, cudaFuncAttributeMaxDynamicSharedMemorySize, PREP_SMEM);
    cudaFuncSetAttribute(kmid_kernel, cudaFuncAttributeMaxDynamicSharedMemorySize, TS_SMEM);

    kprep_all<<<1632, 256, PREP_SMEM>>>(x, ln1g, ln1b, Qw, Kw, w1, w2, outw);

    for (int t = 0; t < 4; ++t) {
        int srcIsG = (t != 0);
        kred1_kernel<<<512, 256>>>();                 // 1024 -> 8 partials
        kmid_kernel<<<32, 256, TS_SMEM>>>(Vw);        // T1 = G@Vw ; Mt = split(QK@T1)
        kc_mma<<<NTILESm, 256, KC_SMEM>>>(x, srcIsG, ln1g, ln1b, ln2g, ln2b,
                                          b1, b2, outb, out, t == 3);
    }
}